// round 3
// baseline (speedup 1.0000x reference)
#include <cuda_runtime.h>
#include <math.h>

// Problem constants
#define NQ   32768      // N*S1*S2
#define MOFF 27

// Attention tiling: 32 queries (2n x 4a x 4b), halo 4n x 6a x 6b = 144 positions
#define HSZ  144
#define WM   4096                          // one 64x64 matrix (floats)
#define ATTN_SMEM ((HSZ * 64 + 2 * WM) * 4)   // 69632 bytes -> 3 CTAs/SM

// Scratch (static device globals: allocation-free per harness rules)
__device__ float g_h0[NQ * 64];
__device__ float g_h1[NQ * 64];
__device__ float g_stats[8];               // mean[0..2], rsigma[4..6]
__device__ float g_wq[2 * WM];             // per layer: [cp4][c][j]
__device__ float g_wkv[2 * MOFF * 2 * WM]; // [layer][m][mat(k,v)][cp4][c][j]

typedef unsigned long long ull;

__device__ __forceinline__ ull pack2(float x, float y) {
    ull r;
    asm("mov.b64 %0, {%1, %2};" : "=l"(r) : "r"(__float_as_uint(x)), "r"(__float_as_uint(y)));
    return r;
}
__device__ __forceinline__ void unpack2(ull p, float& x, float& y) {
    unsigned lo, hi;
    asm("mov.b64 {%0, %1}, %2;" : "=r"(lo), "=r"(hi) : "l"(p));
    x = __uint_as_float(lo); y = __uint_as_float(hi);
}
// Packed dual FP32 FMA (Blackwell FFMA2)
__device__ __forceinline__ ull ffma2(ull a, ull b, ull c) {
    ull d;
    asm("fma.rn.f32x2 %0, %1, %2, %3;" : "=l"(d) : "l"(a), "l"(b), "l"(c));
    return d;
}
__device__ __forceinline__ void cp_async16(float* dst, const float* src) {
    unsigned d = (unsigned)__cvta_generic_to_shared(dst);
    asm volatile("cp.async.cg.shared.global [%0], [%1], 16;" :: "r"(d), "l"(src));
}
__device__ __forceinline__ void cp_commit() {
    asm volatile("cp.async.commit_group;" ::: "memory");
}
__device__ __forceinline__ void cp_wait0() {
    asm volatile("cp.async.wait_group 0;" ::: "memory");
}

// ---------------------------------------------------------------------------
// 0) Weight repack: w[cin][cout] -> [cp4=cin/4][cout][j=cin%4]
// ---------------------------------------------------------------------------
__global__ void repack_w_kernel(const float* __restrict__ Wq,
                                const float* __restrict__ Wk,
                                const float* __restrict__ Wv) {
    int idx = blockIdx.x * 256 + threadIdx.x;
    if (idx < 54 * 4096) {
        int mi = idx >> 12;                 // layer*27 + m
        int e  = idx & 4095;
        int cin = e >> 6, cout = e & 63;
        int o = ((cin >> 2) << 8) + (cout << 2) + (cin & 3);
        g_wkv[mi * 2 * WM + o]      = Wk[idx];
        g_wkv[mi * 2 * WM + WM + o] = Wv[idx];
    }
    if (idx < 2 * 4096) {
        int mi = idx >> 12;
        int e  = idx & 4095;
        int cin = e >> 6, cout = e & 63;
        int o = ((cin >> 2) << 8) + (cout << 2) + (cin & 3);
        g_wq[mi * WM + o] = Wq[idx];
    }
}

// ---------------------------------------------------------------------------
// 1) BatchNorm batch statistics
// ---------------------------------------------------------------------------
__global__ void bn_stats_kernel(const float* __restrict__ x) {
    float s0 = 0.f, s1 = 0.f, s2 = 0.f, t0 = 0.f, t1 = 0.f, t2 = 0.f;
    for (int p = threadIdx.x; p < NQ; p += 1024) {
        float v0 = x[p * 3 + 0], v1 = x[p * 3 + 1], v2 = x[p * 3 + 2];
        s0 += v0; s1 += v1; s2 += v2;
        t0 += v0 * v0; t1 += v1 * v1; t2 += v2 * v2;
    }
#pragma unroll
    for (int o = 16; o; o >>= 1) {
        s0 += __shfl_xor_sync(0xffffffffu, s0, o);
        s1 += __shfl_xor_sync(0xffffffffu, s1, o);
        s2 += __shfl_xor_sync(0xffffffffu, s2, o);
        t0 += __shfl_xor_sync(0xffffffffu, t0, o);
        t1 += __shfl_xor_sync(0xffffffffu, t1, o);
        t2 += __shfl_xor_sync(0xffffffffu, t2, o);
    }
    __shared__ float red[32][6];
    int lane = threadIdx.x & 31, w = threadIdx.x >> 5;
    if (lane == 0) {
        red[w][0] = s0; red[w][1] = s1; red[w][2] = s2;
        red[w][3] = t0; red[w][4] = t1; red[w][5] = t2;
    }
    __syncthreads();
    if (threadIdx.x < 32) {
        float a0 = red[lane][0], a1 = red[lane][1], a2 = red[lane][2];
        float a3 = red[lane][3], a4 = red[lane][4], a5 = red[lane][5];
#pragma unroll
        for (int o = 16; o; o >>= 1) {
            a0 += __shfl_xor_sync(0xffffffffu, a0, o);
            a1 += __shfl_xor_sync(0xffffffffu, a1, o);
            a2 += __shfl_xor_sync(0xffffffffu, a2, o);
            a3 += __shfl_xor_sync(0xffffffffu, a3, o);
            a4 += __shfl_xor_sync(0xffffffffu, a4, o);
            a5 += __shfl_xor_sync(0xffffffffu, a5, o);
        }
        if (lane == 0) {
            const float inv = 1.0f / (float)NQ;
            float m0 = a0 * inv, m1 = a1 * inv, m2 = a2 * inv;
            g_stats[0] = m0; g_stats[1] = m1; g_stats[2] = m2;
            g_stats[4] = rsqrtf(a3 * inv - m0 * m0 + 1e-5f);
            g_stats[5] = rsqrtf(a4 * inv - m1 * m1 + 1e-5f);
            g_stats[6] = rsqrtf(a5 * inv - m2 * m2 + 1e-5f);
        }
    }
}

// ---------------------------------------------------------------------------
// 2) h0 = normalize(x) @ W_in + b_in
// ---------------------------------------------------------------------------
__global__ void input_proj_kernel(const float* __restrict__ x,
                                  const float* __restrict__ W_in,
                                  const float* __restrict__ b_in,
                                  float* __restrict__ h_out) {
    int idx = blockIdx.x * 256 + threadIdx.x;
    int p = idx >> 6, c = idx & 63;
    float acc = b_in[c];
#pragma unroll
    for (int f = 0; f < 3; f++) {
        float xn = (x[p * 3 + f] - g_stats[f]) * g_stats[4 + f];
        acc += xn * W_in[f * 64 + c];
    }
    h_out[idx] = acc;
}

// ---------------------------------------------------------------------------
// 3) Fused attention layer. 256 threads = 64 channels x 4 query-slots.
//    Slot = qa row; thread handles 8 queries (2 qn x 4 qb), one channel.
//    Scores are tiny (weights*0.05 init scale), so plain exp (no max-sub) is
//    numerically safe and softmax-invariant; masked offsets get p = 0.
// ---------------------------------------------------------------------------
__global__ __launch_bounds__(256, 3)
void attn_kernel(const float* __restrict__ h_in, float* __restrict__ h_out,
                 const float* __restrict__ wq, const float* __restrict__ bq,
                 const float* __restrict__ wkv,
                 const float* __restrict__ bk, const float* __restrict__ bv) {
    extern __shared__ float smem[];
    float* h_s = smem;                 // 144 * 64
    float* w_s = smem + HSZ * 64;      // 2 * WM (k then v)

    const int tid  = threadIdx.x;
    const int lane = tid & 31;
    const int warp = tid >> 5;                   // 0..7
    const int c    = ((warp & 1) << 5) + lane;   // output channel 0..63
    const int slot = warp >> 1;                  // qa = 0..3

    const int bx  = blockIdx.x;
    const int tn2 = bx >> 6;
    const int r   = bx & 63;
    const int a0  = ((r >> 3) & 7) << 2;
    const int b0  = (r & 7) << 2;
    const int n0  = tn2 << 1;

    // --- halo load: 144 pos x 64 ch, zero OOB ---
    for (int idx = tid; idx < HSZ * 16; idx += 256) {
        int pos = idx >> 4, c4 = idx & 15;
        int hn = pos / 36, rem = pos - hn * 36;
        int ha = rem / 6, hb = rem - ha * 6;
        int gn = n0 - 1 + hn, ga = a0 - 1 + ha, gb = b0 - 1 + hb;
        float4 v = make_float4(0.f, 0.f, 0.f, 0.f);
        if ((unsigned)gn < 32u && (unsigned)ga < 32u && (unsigned)gb < 32u)
            v = *(const float4*)&h_in[(((gn * 32 + ga) * 32 + gb) << 6) + (c4 << 2)];
        *(float4*)&h_s[(pos << 6) + (c4 << 2)] = v;
    }
    // stage Wq
    for (int j = tid; j < WM / 4; j += 256)
        cp_async16(&w_s[j << 2], &wq[j << 2]);
    cp_commit(); cp_wait0();
    __syncthreads();

    // per-thread query geometry: qa = slot; i -> (qn = i>>2, qb = i&3)
    const int ga = a0 + slot;
    const int qbase = slot * 6 + 43;   // halo idx for (qn=0, qb=0): 36 + (qa+1)*6 + 1
    // query halo offsets: qoff[i] = (i>>2)*36 + (i&3)

    // validity bitmask over 27 offsets (spatial only; time is zero-padded)
    unsigned vm[8];
    {
        bool aM = (ga > 0), aP = (ga < 31);
#pragma unroll
        for (int i = 0; i < 8; i++) {
            int gb = b0 + (i & 3);
            bool bM = (gb > 0), bP = (gb < 31);
            unsigned v = 0;
#pragma unroll
            for (int m = 0; m < 27; m++) {
                int r9 = m % 9;
                int di = r9 / 3 - 1, dj = r9 % 3 - 1;
                bool ok = (di < 0 ? aM : (di > 0 ? aP : true)) &&
                          (dj < 0 ? bM : (dj > 0 ? bP : true));
                v |= ((unsigned)ok) << m;
            }
            vm[i] = v;
        }
    }

    // --- q projection: q[c] for 8 queries ---
    float qv[8];
    {
        ull acc[8];
        ull z = pack2(0.0f, 0.0f);
#pragma unroll
        for (int i = 0; i < 8; i++) acc[i] = z;
#pragma unroll
        for (int cp4 = 0; cp4 < 16; cp4++) {
            ulonglong2 w2 = *(const ulonglong2*)&w_s[(cp4 << 8) + (c << 2)];
#pragma unroll
            for (int i = 0; i < 8; i++) {
                int hidx = qbase + (i >> 2) * 36 + (i & 3);
                ulonglong2 hh = *(const ulonglong2*)&h_s[(hidx << 6) + (cp4 << 2)];
                acc[i] = ffma2(hh.x, w2.x, acc[i]);
                acc[i] = ffma2(hh.y, w2.y, acc[i]);
            }
        }
        float bqc = bq[c];
#pragma unroll
        for (int i = 0; i < 8; i++) {
            float x, y; unpack2(acc[i], x, y);
            qv[i] = bqc + x + y;
        }
    }

    float den[8], oacc[8];
#pragma unroll
    for (int i = 0; i < 8; i++) { den[i] = 0.0f; oacc[i] = 0.0f; }

    // --- loop over 27 offsets ---
    for (int m = 0; m < MOFF; m++) {
        __syncthreads();   // previous weights fully consumed
        {
            const float* gsrc = wkv + m * (2 * WM);
            for (int j = tid; j < (2 * WM) / 4; j += 256)
                cp_async16(&w_s[j << 2], gsrc + (j << 2));
            cp_commit(); cp_wait0();
        }
        __syncthreads();

        int t  = m / 9;
        int r9 = m - t * 9;
        int k1 = r9 / 3, k2 = r9 - k1 * 3;
        int dofs = (t - 1) * 36 + (k1 - 1) * 6 + (k2 - 1);

        ull kacc[8], vacc[8];
        {
            ull bkp = pack2(__ldg(&bk[m * 64 + c]), 0.0f);
            ull bvp = pack2(__ldg(&bv[m * 64 + c]), 0.0f);
#pragma unroll
            for (int i = 0; i < 8; i++) { kacc[i] = bkp; vacc[i] = bvp; }
        }

        const float* hrow = h_s + ((qbase + dofs) << 6);
#pragma unroll
        for (int cp4 = 0; cp4 < 16; cp4++) {
            ulonglong2 wk2 = *(const ulonglong2*)&w_s[(cp4 << 8) + (c << 2)];
            ulonglong2 wv2 = *(const ulonglong2*)&w_s[WM + (cp4 << 8) + (c << 2)];
#pragma unroll
            for (int i = 0; i < 8; i++) {
                int ho = ((i >> 2) * 36 + (i & 3)) << 6;
                ulonglong2 hh = *(const ulonglong2*)&hrow[ho + (cp4 << 2)];
                kacc[i] = ffma2(hh.x, wk2.x, kacc[i]);
                vacc[i] = ffma2(hh.x, wv2.x, vacc[i]);
                kacc[i] = ffma2(hh.y, wk2.y, kacc[i]);
                vacc[i] = ffma2(hh.y, wv2.y, vacc[i]);
            }
        }

#pragma unroll
        for (int i = 0; i < 8; i++) {
            float kx, ky; unpack2(kacc[i], kx, ky);
            float s = (kx + ky) * qv[i];
            // sum over this head's 16 channels (16-lane groups)
            s += __shfl_xor_sync(0xffffffffu, s, 1);
            s += __shfl_xor_sync(0xffffffffu, s, 2);
            s += __shfl_xor_sync(0xffffffffu, s, 4);
            s += __shfl_xor_sync(0xffffffffu, s, 8);
            float msel = (float)((vm[i] >> m) & 1u);
            float p = __expf(s) * msel;
            den[i] += p;
            float vx, vy; unpack2(vacc[i], vx, vy);
            oacc[i] += p * (vx + vy);
        }
    }

    // --- epilogue: normalize, residual, write ---
#pragma unroll
    for (int i = 0; i < 8; i++) {
        int hidx = qbase + (i >> 2) * 36 + (i & 3);
        float res = h_s[(hidx << 6) + c];
        int gn = n0 + (i >> 2), gb = b0 + (i & 3);
        int gpos = (gn * 32 + ga) * 32 + gb;
        h_out[(gpos << 6) + c] = oacc[i] / den[i] + res;
    }
}

// ---------------------------------------------------------------------------
// 4) out = h @ W_out + b_out
// ---------------------------------------------------------------------------
__global__ void out_proj_kernel(const float* __restrict__ h,
                                const float* __restrict__ W_out,
                                const float* __restrict__ b_out,
                                float* __restrict__ out) {
    __shared__ float hs[32 * 64];
    int tid = threadIdx.x;              // 128 threads
    int base = blockIdx.x * 32;
    for (int j = tid; j < 2048; j += 128) hs[j] = h[base * 64 + j];
    __syncthreads();
    if (tid < 96) {
        int rr = tid / 3, f = tid - 3 * (tid / 3);
        float acc = b_out[f];
#pragma unroll 8
        for (int cp = 0; cp < 64; cp++)
            acc += hs[rr * 64 + cp] * W_out[cp * 3 + f];
        out[(base + rr) * 3 + f] = acc;
    }
}

// ---------------------------------------------------------------------------
extern "C" void kernel_launch(void* const* d_in, const int* in_sizes, int n_in,
                              void* d_out, int out_size) {
    const float* x     = (const float*)d_in[0];
    const float* W_in  = (const float*)d_in[1];
    const float* b_in  = (const float*)d_in[2];
    const float* W_out = (const float*)d_in[3];
    const float* b_out = (const float*)d_in[4];
    const float* Wq    = (const float*)d_in[5];
    const float* bq    = (const float*)d_in[6];
    const float* Wk    = (const float*)d_in[7];
    const float* bk    = (const float*)d_in[8];
    const float* Wv    = (const float*)d_in[9];
    const float* bv    = (const float*)d_in[10];
    float* out = (float*)d_out;

    float *h0, *h1, *wq, *wkv;
    cudaGetSymbolAddress((void**)&h0, g_h0);
    cudaGetSymbolAddress((void**)&h1, g_h1);
    cudaGetSymbolAddress((void**)&wq, g_wq);
    cudaGetSymbolAddress((void**)&wkv, g_wkv);
    cudaFuncSetAttribute(attn_kernel, cudaFuncAttributeMaxDynamicSharedMemorySize, ATTN_SMEM);

    repack_w_kernel<<<(54 * 4096 + 255) / 256, 256>>>(Wq, Wk, Wv);
    bn_stats_kernel<<<1, 1024>>>(x);
    input_proj_kernel<<<(NQ * 64) / 256, 256>>>(x, W_in, b_in, h0);

    // layer 0: h0 -> h1
    attn_kernel<<<1024, 256, ATTN_SMEM>>>(h0, h1,
        wq + 0 * WM, bq + 0 * 64,
        wkv + 0 * MOFF * 2 * WM,
        bk + 0 * MOFF * 64, bv + 0 * MOFF * 64);
    // layer 1: h1 -> h0
    attn_kernel<<<1024, 256, ATTN_SMEM>>>(h1, h0,
        wq + 1 * WM, bq + 1 * 64,
        wkv + 1 * MOFF * 2 * WM,
        bk + 1 * MOFF * 64, bv + 1 * MOFF * 64);

    out_proj_kernel<<<NQ / 32, 128>>>(h0, W_out, b_out, out);
}

// round 6
// speedup vs baseline: 3.4815x; 3.4815x over previous
#include <cuda_runtime.h>
#include <math.h>
#include <stdint.h>

// Problem constants
#define NQ   32768      // N*S1*S2 linear positions
#define MOFF 27

// --- dynamic smem byte offsets ---
#define A0B  0          // A buffer 0: 128 rows x 64 ch fp32, swizzled (32KB)
#define A1B  32768
#define B0B  65536      // B buffer 0: frag-packed [Khi 16KB | Vhi 16KB | Vlo 16KB]
#define B1B  114688
#define BKB  163840     // bk staged: 27*64 floats
#define BVB  170752     // bv staged
#define BQB  177664     // bq: 64 floats
#define PB   177920     // p_s: 128 queries x 4 heads
#define SMEMB 179968

// Scratch (static device globals: allocation-free per harness rules)
__device__ float g_h0[NQ * 64];
__device__ float g_h1[NQ * 64];
__device__ float g_stats[8];
__device__ float g_wq_p[2 * 4096];      // frag-packed RNA(Wq^T) per layer
__device__ float g_wkv_p[54 * 12288];   // per (layer,m): [Khi | Vhi | Vlo] frag packs

// ---------------------------------------------------------------------------
// helpers
// ---------------------------------------------------------------------------
__device__ __forceinline__ uint32_t smem_u32(const void* p) {
    uint32_t a;
    asm("{ .reg .u64 t; cvta.to.shared.u64 t, %1; cvt.u32.u64 %0, t; }" : "=r"(a) : "l"(p));
    return a;
}
__device__ __forceinline__ float tf32r(float x) {          // round-to-nearest tf32
    unsigned u;
    asm("cvt.rna.tf32.f32 %0, %1;" : "=r"(u) : "f"(x));
    return __uint_as_float(u);
}
__device__ __forceinline__ void cpa16z(uint32_t dst, const float* src, int ok) {
    asm volatile("cp.async.cg.shared.global [%0], [%1], 16, %2;"
                 :: "r"(dst), "l"(src), "r"(ok ? 16 : 0));
}
__device__ __forceinline__ void cpa16(uint32_t dst, const float* src) {
    asm volatile("cp.async.cg.shared.global [%0], [%1], 16;" :: "r"(dst), "l"(src));
}
#define CPA_COMMIT() asm volatile("cp.async.commit_group;" ::: "memory")
#define CPA_WAIT1()  asm volatile("cp.async.wait_group 1;" ::: "memory")
#define CPA_WAIT0()  asm volatile("cp.async.wait_group 0;" ::: "memory")

__device__ __forceinline__ float ldsf(uint32_t a) {
    float v; asm volatile("ld.shared.f32 %0, [%1];" : "=f"(v) : "r"(a)); return v;
}
__device__ __forceinline__ void lds64u(unsigned& x, unsigned& y, uint32_t a) {
    asm volatile("ld.shared.v2.b32 {%0, %1}, [%2];" : "=r"(x), "=r"(y) : "r"(a));
}
__device__ __forceinline__ void lds128f(float& x, float& y, float& z, float& w, uint32_t a) {
    asm volatile("ld.shared.v4.f32 {%0, %1, %2, %3}, [%4];"
                 : "=f"(x), "=f"(y), "=f"(z), "=f"(w) : "r"(a));
}
__device__ __forceinline__ void stsf(uint32_t a, float v) {
    asm volatile("st.shared.f32 [%0], %1;" :: "r"(a), "f"(v));
}
// baseline PTX tensor-core mma (sm_80+): D(16x8) += A(16x8,tf32) * B(8x8,tf32)
__device__ __forceinline__ void mma8(float* d, const unsigned* a, unsigned b0, unsigned b1) {
    asm volatile(
        "mma.sync.aligned.m16n8k8.row.col.f32.tf32.tf32.f32 "
        "{%0,%1,%2,%3}, {%4,%5,%6,%7}, {%8,%9}, {%0,%1,%2,%3};"
        : "+f"(d[0]), "+f"(d[1]), "+f"(d[2]), "+f"(d[3])
        : "r"(a[0]), "r"(a[1]), "r"(a[2]), "r"(a[3]), "r"(b0), "r"(b1));
}

// ---------------------------------------------------------------------------
// 0) Weight repack to per-lane mma fragment order (+ tf32 rounding/splitting).
//    Fragment fp=(j*8+ks), lane l, half hf:
//    Bp[fp*64 + l*2 + hf] = W[cin = 8ks + (l&3) + 4hf][cout = 8j + (l>>2)]
//    Packs per (layer,m): [Khi | Vhi | Vlo];  Wq: hi only.
// ---------------------------------------------------------------------------
__global__ void repack_w_kernel(const float* __restrict__ Wq,
                                const float* __restrict__ Wk,
                                const float* __restrict__ Wv) {
    int idx = blockIdx.x * 256 + threadIdx.x;
    if (idx < 54 * 4096) {
        int mi = idx >> 12, e = idx & 4095;
        int fp = e >> 6, ln = (e >> 1) & 31, hf = e & 1;
        int ks = fp & 7, j = fp >> 3;
        int cin  = 8 * ks + (ln & 3) + 4 * hf;
        int cout = 8 * j + (ln >> 2);
        int src  = mi * 4096 + cin * 64 + cout;
        float wk = Wk[src], wv = Wv[src];
        float vhi = tf32r(wv);
        g_wkv_p[mi * 12288 + e]        = tf32r(wk);        // Khi
        g_wkv_p[mi * 12288 + 4096 + e] = vhi;              // Vhi
        g_wkv_p[mi * 12288 + 8192 + e] = tf32r(wv - vhi);  // Vlo
        if (mi < 2)
            g_wq_p[mi * 4096 + e] = tf32r(Wq[src]);
    }
}

// ---------------------------------------------------------------------------
// 1) BatchNorm batch statistics
// ---------------------------------------------------------------------------
__global__ void bn_stats_kernel(const float* __restrict__ x) {
    float s0 = 0.f, s1 = 0.f, s2 = 0.f, t0 = 0.f, t1 = 0.f, t2 = 0.f;
    for (int p = threadIdx.x; p < NQ; p += 1024) {
        float v0 = x[p * 3 + 0], v1 = x[p * 3 + 1], v2 = x[p * 3 + 2];
        s0 += v0; s1 += v1; s2 += v2;
        t0 += v0 * v0; t1 += v1 * v1; t2 += v2 * v2;
    }
#pragma unroll
    for (int o = 16; o; o >>= 1) {
        s0 += __shfl_xor_sync(0xffffffffu, s0, o);
        s1 += __shfl_xor_sync(0xffffffffu, s1, o);
        s2 += __shfl_xor_sync(0xffffffffu, s2, o);
        t0 += __shfl_xor_sync(0xffffffffu, t0, o);
        t1 += __shfl_xor_sync(0xffffffffu, t1, o);
        t2 += __shfl_xor_sync(0xffffffffu, t2, o);
    }
    __shared__ float red[32][6];
    int lane = threadIdx.x & 31, w = threadIdx.x >> 5;
    if (lane == 0) {
        red[w][0] = s0; red[w][1] = s1; red[w][2] = s2;
        red[w][3] = t0; red[w][4] = t1; red[w][5] = t2;
    }
    __syncthreads();
    if (threadIdx.x < 32) {
        float a0 = red[lane][0], a1 = red[lane][1], a2 = red[lane][2];
        float a3 = red[lane][3], a4 = red[lane][4], a5 = red[lane][5];
#pragma unroll
        for (int o = 16; o; o >>= 1) {
            a0 += __shfl_xor_sync(0xffffffffu, a0, o);
            a1 += __shfl_xor_sync(0xffffffffu, a1, o);
            a2 += __shfl_xor_sync(0xffffffffu, a2, o);
            a3 += __shfl_xor_sync(0xffffffffu, a3, o);
            a4 += __shfl_xor_sync(0xffffffffu, a4, o);
            a5 += __shfl_xor_sync(0xffffffffu, a5, o);
        }
        if (lane == 0) {
            const float inv = 1.0f / (float)NQ;
            float m0 = a0 * inv, m1 = a1 * inv, m2 = a2 * inv;
            g_stats[0] = m0; g_stats[1] = m1; g_stats[2] = m2;
            g_stats[4] = rsqrtf(a3 * inv - m0 * m0 + 1e-5f);
            g_stats[5] = rsqrtf(a4 * inv - m1 * m1 + 1e-5f);
            g_stats[6] = rsqrtf(a5 * inv - m2 * m2 + 1e-5f);
        }
    }
}

// ---------------------------------------------------------------------------
// 2) h0 = normalize(x) @ W_in + b_in
// ---------------------------------------------------------------------------
__global__ void input_proj_kernel(const float* __restrict__ x,
                                  const float* __restrict__ W_in,
                                  const float* __restrict__ b_in,
                                  float* __restrict__ h_out) {
    int idx = blockIdx.x * 256 + threadIdx.x;
    int p = idx >> 6, c = idx & 63;
    float acc = b_in[c];
#pragma unroll
    for (int f = 0; f < 3; f++) {
        float xn = (x[p * 3 + f] - g_stats[f]) * g_stats[4 + f];
        acc += xn * W_in[f * 64 + c];
    }
    h_out[idx] = acc;
}

// ---------------------------------------------------------------------------
// A staging: 128 rows x 64 ch into XOR-swizzled smem (16B blocks), zero rows
// whose linear pos is outside [0, NQ)  == reference time zero-padding.
// ---------------------------------------------------------------------------
__device__ __forceinline__ void stageA(uint32_t sb, uint32_t abuf,
                                       const float* __restrict__ h, int pos0, int tid) {
#pragma unroll
    for (int i = 0; i < 8; i++) {
        int u = tid + (i << 8);          // 0..2047
        int row = u >> 4, c4 = u & 15;
        uint32_t dst = sb + abuf + (row << 8) + ((c4 ^ (row & 7)) << 4);
        int pos = pos0 + row;
        int ok = ((unsigned)pos < (unsigned)NQ);
        const float* src = h + ((size_t)(ok ? pos : 0) << 6) + (c4 << 2);
        cpa16z(dst, src, ok);
    }
}
__device__ __forceinline__ void stageB(uint32_t sb, uint32_t bbuf,
                                       const float* __restrict__ w, int tid) {
#pragma unroll
    for (int i = 0; i < 12; i++) {
        int u = tid + (i << 8);          // 0..3071 (48KB)
        cpa16(sb + bbuf + (u << 4), w + (u << 2));
    }
}

// single-tf32 128x64x64 GEMM (warp-tile 32x64), A rounded RNA at load
__device__ __forceinline__ void mma_K(float* d, uint32_t aB, uint32_t bB,
                                      int l4, int lane) {
#pragma unroll
    for (int e = 0; e < 64; e++) d[e] = 0.0f;
#pragma unroll
    for (int ks = 0; ks < 8; ks++) {
        unsigned a[2][4];
        uint32_t o0 = (uint32_t)(((2 * ks) ^ l4) << 4);
        uint32_t o1 = (uint32_t)(((2 * ks + 1) ^ l4) << 4);
#pragma unroll
        for (int mt = 0; mt < 2; mt++) {
            uint32_t base = aB + (mt << 12);
            a[mt][0] = __float_as_uint(tf32r(ldsf(base + o0)));
            a[mt][1] = __float_as_uint(tf32r(ldsf(base + o0 + 2048)));
            a[mt][2] = __float_as_uint(tf32r(ldsf(base + o1)));
            a[mt][3] = __float_as_uint(tf32r(ldsf(base + o1 + 2048)));
        }
#pragma unroll
        for (int j = 0; j < 8; j++) {
            unsigned b0, b1;
            lds64u(b0, b1, bB + (uint32_t)(((j << 3) + ks) << 8) + (lane << 3));
            mma8(&d[j << 2],       a[0], b0, b1);
            mma8(&d[(8 + j) << 2], a[1], b0, b1);
        }
    }
}

// split-tf32 (3-term) 128x64x64 GEMM: d = Ahi*Bhi + Alo*Bhi + Ahi*Blo
__device__ __forceinline__ void mma_V3(float* d, uint32_t aB, uint32_t bHi,
                                       uint32_t bLo, int l4, int lane) {
#pragma unroll
    for (int e = 0; e < 64; e++) d[e] = 0.0f;
#pragma unroll
    for (int ks = 0; ks < 8; ks++) {
        unsigned ahi[2][4], alo[2][4];
        uint32_t o0 = (uint32_t)(((2 * ks) ^ l4) << 4);
        uint32_t o1 = (uint32_t)(((2 * ks + 1) ^ l4) << 4);
#pragma unroll
        for (int mt = 0; mt < 2; mt++) {
            uint32_t base = aB + (mt << 12);
            float f0 = ldsf(base + o0);
            float f1 = ldsf(base + o0 + 2048);
            float f2 = ldsf(base + o1);
            float f3 = ldsf(base + o1 + 2048);
            float h0 = tf32r(f0), h1 = tf32r(f1), h2 = tf32r(f2), h3 = tf32r(f3);
            ahi[mt][0] = __float_as_uint(h0);
            ahi[mt][1] = __float_as_uint(h1);
            ahi[mt][2] = __float_as_uint(h2);
            ahi[mt][3] = __float_as_uint(h3);
            alo[mt][0] = __float_as_uint(tf32r(f0 - h0));
            alo[mt][1] = __float_as_uint(tf32r(f1 - h1));
            alo[mt][2] = __float_as_uint(tf32r(f2 - h2));
            alo[mt][3] = __float_as_uint(tf32r(f3 - h3));
        }
#pragma unroll
        for (int j = 0; j < 8; j++) {
            uint32_t fo = (uint32_t)(((j << 3) + ks) << 8) + (lane << 3);
            unsigned bh0, bh1, bl0, bl1;
            lds64u(bh0, bh1, bHi + fo);
            lds64u(bl0, bl1, bLo + fo);
#pragma unroll
            for (int mt = 0; mt < 2; mt++) {
                float* dd = &d[(mt * 8 + j) << 2];
                mma8(dd, ahi[mt], bh0, bh1);
                mma8(dd, alo[mt], bh0, bh1);
                mma8(dd, ahi[mt], bl0, bl1);
            }
        }
    }
}

// ---------------------------------------------------------------------------
// 3) Fused attention layer, tensor-core (mma.sync tf32).
//    256 threads = 8 warps: mw = wid&3 owns 32 queries (rows 32mw..+32);
//    role = wid>>2: 0 = K-side (Q frags, scores, p), 1 = V-side (3x-split V).
// ---------------------------------------------------------------------------
__global__ __launch_bounds__(256, 1)
void attn_mma_kernel(const float* __restrict__ h_in, float* __restrict__ h_out,
                     const float* __restrict__ wq_p, const float* __restrict__ bq,
                     const float* __restrict__ wkv_p,
                     const float* __restrict__ bk, const float* __restrict__ bv) {
    extern __shared__ float smem[];
    const uint32_t sb = smem_u32(smem);
    const int tid  = threadIdx.x;
    const int lane = tid & 31;
    const int wid  = tid >> 5;
    const int tig  = lane & 3;
    const int l4   = lane >> 2;
    const int mw   = wid & 3;
    const int role = wid >> 2;

    const int bx    = blockIdx.x;
    const int tbase = bx << 7;                 // 128 consecutive queries
    const int a0    = (bx & 7) << 2;

    const uint32_t aOff = (uint32_t)(((mw << 5) + l4) << 8) + (tig << 2);

    // ---- prologue staging ----
    stageA(sb, A0B, h_in, tbase, tid);
#pragma unroll
    for (int i = 0; i < 4; i++) {
        int u = tid + (i << 8);                 // 0..1023
        cpa16(sb + B0B + (u << 4), wq_p + (u << 2));
    }
#pragma unroll
    for (int i = 0; i < 4; i++) {
        int u = tid + (i << 8);
        if (u < 432)      cpa16(sb + BKB + (u << 4), bk + (u << 2));
        else if (u < 864) cpa16(sb + BVB + ((u - 432) << 4), bv + ((u - 432) << 2));
        else if (u < 880) cpa16(sb + BQB + ((u - 864) << 4), bq + ((u - 864) << 2));
    }
    CPA_COMMIT();
    stageA(sb, A1B, h_in, tbase - 1024 - 32 - 1, tid);   // m=0: dt=-1,di=-1,dj=-1
    stageB(sb, B1B, wkv_p, tid);
    CPA_COMMIT();
    CPA_WAIT1();          // group0 (A0, wq, biases) complete
    __syncthreads();

    // ---- per-thread query geometry & spatial masks ----
    const int ga = a0 + mw;
    unsigned vm[4];
#pragma unroll
    for (int qi = 0; qi < 4; qi++) {
        int gb = l4 + ((qi >> 1) << 4) + ((qi & 1) << 3);
        unsigned v = 0;
#pragma unroll
        for (int m = 0; m < MOFF; m++) {
            int r9 = m % 9;
            int di = r9 / 3 - 1, dj = r9 % 3 - 1;
            bool ok = ((unsigned)(ga + di) < 32u) && ((unsigned)(gb + dj) < 32u);
            v |= ((unsigned)ok) << m;
        }
        vm[qi] = v;
    }

    // ---- acc: role0 -> q fragments (Q GEMM + bq); role1 -> output accum ----
    float acc[64];
    float den[4][4];
#pragma unroll
    for (int qi = 0; qi < 4; qi++)
#pragma unroll
        for (int h = 0; h < 4; h++) den[qi][h] = 0.0f;

    if (role == 0) {
        mma_K(acc, sb + A0B + aOff, sb + B0B, l4, lane);
#pragma unroll
        for (int j = 0; j < 8; j++)
#pragma unroll
            for (int u = 0; u < 2; u++) {
                float bqc = ldsf(sb + BQB + ((8 * j + 2 * tig + u) << 2));
#pragma unroll
                for (int mt = 0; mt < 2; mt++)
#pragma unroll
                    for (int rh = 0; rh < 2; rh++)
                        acc[(mt * 8 + j) * 4 + rh * 2 + u] += bqc;
            }
    } else {
#pragma unroll
        for (int e = 0; e < 64; e++) acc[e] = 0.0f;
    }
    __syncthreads();     // A0/B0 free before iter-0 prefetch targets them

    float d[64];

    // ---- 27-offset mainloop, double-buffered ----
    for (int m = 0; m < MOFF; m++) {
        const uint32_t curA = (m & 1) ? A0B : A1B;
        const uint32_t curB = (m & 1) ? B0B : B1B;
        if (m < MOFF - 1) {
            int mn = m + 1;
            int t = mn / 9, r9 = mn % 9;
            int pos0 = tbase + (t - 1) * 1024 + (r9 / 3 - 1) * 32 + (r9 % 3 - 1);
            stageA(sb, (m & 1) ? A1B : A0B, h_in, pos0, tid);
            stageB(sb, (m & 1) ? B1B : B0B, wkv_p + mn * 12288, tid);
            CPA_COMMIT();
            CPA_WAIT1();
        } else {
            CPA_WAIT0();
        }
        __syncthreads();     // staged data visible to all warps

        if (role == 0) {
            // K projection (single tf32) -> scores
            mma_K(d, sb + curA + aOff, sb + curB, l4, lane);

            float bkc[16];
#pragma unroll
            for (int j = 0; j < 8; j++)
#pragma unroll
                for (int u = 0; u < 2; u++)
                    bkc[j * 2 + u] = ldsf(sb + BKB + (m << 8) + ((8 * j + 2 * tig + u) << 2));
            float sp[16];
#pragma unroll
            for (int t = 0; t < 16; t++) sp[t] = 0.0f;
#pragma unroll
            for (int mt = 0; mt < 2; mt++)
#pragma unroll
                for (int j = 0; j < 8; j++)
#pragma unroll
                    for (int rh = 0; rh < 2; rh++)
#pragma unroll
                        for (int u = 0; u < 2; u++) {
                            int di = (mt * 8 + j) * 4 + rh * 2 + u;
                            float kk = d[di] + bkc[j * 2 + u];
                            sp[(mt * 2 + rh) * 4 + (j >> 1)] += kk * acc[di];
                        }
#pragma unroll
            for (int t = 0; t < 16; t++) {
                sp[t] += __shfl_xor_sync(0xffffffffu, sp[t], 1);
                sp[t] += __shfl_xor_sync(0xffffffffu, sp[t], 2);
            }
#pragma unroll
            for (int qi = 0; qi < 4; qi++) {
                float s = (tig == 0) ? sp[qi * 4 + 0]
                        : (tig == 1) ? sp[qi * 4 + 1]
                        : (tig == 2) ? sp[qi * 4 + 2] : sp[qi * 4 + 3];
                bool ok = (vm[qi] >> m) & 1u;
                float p = __expf(ok ? s : -1e30f);    // mask BEFORE exp
                int gb = l4 + ((qi >> 1) << 4) + ((qi & 1) << 3);
                stsf(sb + PB + (uint32_t)((((mw << 5) + gb) << 2) + tig) * 4, p);
            }
        } else {
            // V projection (split tf32, 3 MMA terms)
            mma_V3(d, sb + curA + aOff, sb + curB + 16384u, sb + curB + 32768u,
                   l4, lane);
        }
        __syncthreads();     // p_s published; all buffer reads complete

        if (role == 1) {
            float bvc[16];
#pragma unroll
            for (int j = 0; j < 8; j++)
#pragma unroll
                for (int u = 0; u < 2; u++)
                    bvc[j * 2 + u] = ldsf(sb + BVB + (m << 8) + ((8 * j + 2 * tig + u) << 2));
            float p4[4][4];
#pragma unroll
            for (int qi = 0; qi < 4; qi++) {
                int gb = l4 + ((qi >> 1) << 4) + ((qi & 1) << 3);
                lds128f(p4[qi][0], p4[qi][1], p4[qi][2], p4[qi][3],
                        sb + PB + (uint32_t)((((mw << 5) + gb) << 2)) * 4);
#pragma unroll
                for (int h = 0; h < 4; h++) den[qi][h] += p4[qi][h];   // per-head!
            }
#pragma unroll
            for (int mt = 0; mt < 2; mt++)
#pragma unroll
                for (int j = 0; j < 8; j++)
#pragma unroll
                    for (int rh = 0; rh < 2; rh++)
#pragma unroll
                        for (int u = 0; u < 2; u++) {
                            int di = (mt * 8 + j) * 4 + rh * 2 + u;
                            float vv = d[di] + bvc[j * 2 + u];
                            acc[di] += p4[mt * 2 + rh][j >> 1] * vv;
                        }
        }
    }

    // ---- epilogue (V-warps own all output channels) ----
    if (role == 1) {
#pragma unroll
        for (int qi = 0; qi < 4; qi++) {
            int gb = l4 + ((qi >> 1) << 4) + ((qi & 1) << 3);
            int pos = tbase + (mw << 5) + gb;
            float inv[4];
#pragma unroll
            for (int h = 0; h < 4; h++) inv[h] = 1.0f / den[qi][h];
            const float* rp = h_in + ((size_t)pos << 6);
            float* op = h_out + ((size_t)pos << 6);
            int mt = qi >> 1, rh = qi & 1;
#pragma unroll
            for (int j = 0; j < 8; j++) {
                int c = 8 * j + 2 * tig;
                float2 r = *(const float2*)(rp + c);
                float2 o;
                float iv = inv[j >> 1];              // head = channel/16 = j>>1
                o.x = acc[(mt * 8 + j) * 4 + rh * 2 + 0] * iv + r.x;
                o.y = acc[(mt * 8 + j) * 4 + rh * 2 + 1] * iv + r.y;
                *(float2*)(op + c) = o;
            }
        }
    }
}

// ---------------------------------------------------------------------------
// 4) out = h @ W_out + b_out
// ---------------------------------------------------------------------------
__global__ void out_proj_kernel(const float* __restrict__ h,
                                const float* __restrict__ W_out,
                                const float* __restrict__ b_out,
                                float* __restrict__ out) {
    __shared__ float hs[32 * 64];
    int tid = threadIdx.x;              // 128 threads
    int base = blockIdx.x * 32;
    for (int j = tid; j < 2048; j += 128) hs[j] = h[base * 64 + j];
    __syncthreads();
    if (tid < 96) {
        int rr = tid / 3, f = tid - 3 * (tid / 3);
        float acc = b_out[f];
#pragma unroll 8
        for (int cp = 0; cp < 64; cp++)
            acc += hs[rr * 64 + cp] * W_out[cp * 3 + f];
        out[(base + rr) * 3 + f] = acc;
    }
}

// ---------------------------------------------------------------------------
extern "C" void kernel_launch(void* const* d_in, const int* in_sizes, int n_in,
                              void* d_out, int out_size) {
    const float* x     = (const float*)d_in[0];
    const float* W_in  = (const float*)d_in[1];
    const float* b_in  = (const float*)d_in[2];
    const float* W_out = (const float*)d_in[3];
    const float* b_out = (const float*)d_in[4];
    const float* Wq    = (const float*)d_in[5];
    const float* bq    = (const float*)d_in[6];
    const float* Wk    = (const float*)d_in[7];
    const float* bk    = (const float*)d_in[8];
    const float* Wv    = (const float*)d_in[9];
    const float* bv    = (const float*)d_in[10];
    float* out = (float*)d_out;

    float *h0, *h1, *wq_p, *wkv_p;
    cudaGetSymbolAddress((void**)&h0, g_h0);
    cudaGetSymbolAddress((void**)&h1, g_h1);
    cudaGetSymbolAddress((void**)&wq_p, g_wq_p);
    cudaGetSymbolAddress((void**)&wkv_p, g_wkv_p);
    cudaFuncSetAttribute(attn_mma_kernel, cudaFuncAttributeMaxDynamicSharedMemorySize, SMEMB);

    repack_w_kernel<<<(54 * 4096 + 255) / 256, 256>>>(Wq, Wk, Wv);
    bn_stats_kernel<<<1, 1024>>>(x);
    input_proj_kernel<<<(NQ * 64) / 256, 256>>>(x, W_in, b_in, h0);

    // layer 0: h0 -> h1
    attn_mma_kernel<<<256, 256, SMEMB>>>(h0, h1,
        wq_p + 0 * 4096, bq + 0 * 64,
        wkv_p + 0 * MOFF * 12288,
        bk + 0 * MOFF * 64, bv + 0 * MOFF * 64);
    // layer 1: h1 -> h0
    attn_mma_kernel<<<256, 256, SMEMB>>>(h1, h0,
        wq_p + 1 * 4096, bq + 1 * 64,
        wkv_p + 1 * MOFF * 12288,
        bk + 1 * MOFF * 64, bv + 1 * MOFF * 64);

    out_proj_kernel<<<NQ / 32, 128>>>(h0, W_out, b_out, out);
}

// round 7
// speedup vs baseline: 5.7325x; 1.6465x over previous
#include <cuda_runtime.h>
#include <cuda_bf16.h>
#include <math.h>
#include <stdint.h>

#define NQ   32768
#define MOFF 27

// smem byte offsets: A region hi/lo (195 rows x 128B each) + 2 B buffers (24KB)
#define ARH  0
#define ARL  24960
#define BB0  49920
#define BB1  74496
#define SMEMB 99072

// Scratch (static device globals: allocation-free per harness rules)
__device__ float g_h0[NQ * 64];
__device__ float g_h1[NQ * 64];
__device__ __nv_bfloat16 g_hbA[2 * NQ * 64];   // [hi plane | lo plane]
__device__ __nv_bfloat16 g_hbB[2 * NQ * 64];
__device__ float g_stats[8];
__device__ unsigned g_wq_pb[2 * 2048];         // frag-packed bf16 Wq^T per layer
__device__ unsigned g_wkv_pb[54 * 6144];       // per (layer,m): [Khi|Vhi|Vlo] 2048 u32 each

// ---------------------------------------------------------------------------
// helpers
// ---------------------------------------------------------------------------
__device__ __forceinline__ uint32_t smem_u32(const void* p) {
    uint32_t a;
    asm("{ .reg .u64 t; cvta.to.shared.u64 t, %1; cvt.u32.u64 %0, t; }" : "=r"(a) : "l"(p));
    return a;
}
__device__ __forceinline__ void cpa16z(uint32_t dst, const void* src, int ok) {
    asm volatile("cp.async.cg.shared.global [%0], [%1], 16, %2;"
                 :: "r"(dst), "l"(src), "r"(ok ? 16 : 0));
}
__device__ __forceinline__ void cpa16(uint32_t dst, const void* src) {
    asm volatile("cp.async.cg.shared.global [%0], [%1], 16;" :: "r"(dst), "l"(src));
}
#define CPA_COMMIT() asm volatile("cp.async.commit_group;" ::: "memory")
#define CPA_WAIT0()  asm volatile("cp.async.wait_group 0;"  ::: "memory")

__device__ __forceinline__ unsigned lds32u(uint32_t a) {
    unsigned v; asm volatile("ld.shared.b32 %0, [%1];" : "=r"(v) : "r"(a)); return v;
}
__device__ __forceinline__ void lds64u(unsigned& x, unsigned& y, uint32_t a) {
    asm volatile("ld.shared.v2.b32 {%0, %1}, [%2];" : "=r"(x), "=r"(y) : "r"(a));
}
// bf16 tensor-core mma (sm_80+ baseline PTX): D(16x8,f32) += A(16x16) * B(16x8)
__device__ __forceinline__ void mma16(float* d, const unsigned* a, unsigned b0, unsigned b1) {
    asm volatile(
        "mma.sync.aligned.m16n8k16.row.col.f32.bf16.bf16.f32 "
        "{%0,%1,%2,%3}, {%4,%5,%6,%7}, {%8,%9}, {%0,%1,%2,%3};"
        : "+f"(d[0]), "+f"(d[1]), "+f"(d[2]), "+f"(d[3])
        : "r"(a[0]), "r"(a[1]), "r"(a[2]), "r"(a[3]), "r"(b0), "r"(b1));
}
__device__ __forceinline__ unsigned packbf2(float x, float y) {
    __nv_bfloat162 t = __floats2bfloat162_rn(x, y);   // .x = x (low), .y = y (high)
    return *reinterpret_cast<unsigned*>(&t);
}

// ---------------------------------------------------------------------------
// 0) Weight repack: per-lane m16n8k16 bf16 fragment order.
//    frag fp = j*4+ks (j: n-tile 0..7, ks: k16-step 0..3); u32 r = l*2+b:
//    cin0 = 16ks + 2(l&3) + 8b;  cout = 8j + (l>>2);  u32 = {W[cin0], W[cin0+1]}
// ---------------------------------------------------------------------------
__global__ void repack_w_kernel(const float* __restrict__ Wq,
                                const float* __restrict__ Wk,
                                const float* __restrict__ Wv) {
    int idx = blockIdx.x * 256 + threadIdx.x;
    if (idx >= 54 * 2048) return;
    int mi = idx >> 11, e = idx & 2047;
    int fp = e >> 6, r = e & 63;
    int l = r >> 1, b = r & 1;
    int ks = fp & 3, j = fp >> 2;
    int cin  = 16 * ks + 2 * (l & 3) + 8 * b;
    int cout = 8 * j + (l >> 2);
    int s0 = mi * 4096 + cin * 64 + cout;
    g_wkv_pb[mi * 6144 + e] = packbf2(Wk[s0], Wk[s0 + 64]);
    float v0 = Wv[s0], v1 = Wv[s0 + 64];
    __nv_bfloat162 vh = __floats2bfloat162_rn(v0, v1);
    g_wkv_pb[mi * 6144 + 2048 + e] = *reinterpret_cast<unsigned*>(&vh);
    g_wkv_pb[mi * 6144 + 4096 + e] =
        packbf2(v0 - __bfloat162float(vh.x), v1 - __bfloat162float(vh.y));
    if (mi < 2)
        g_wq_pb[mi * 2048 + e] = packbf2(Wq[s0], Wq[s0 + 64]);
}

// ---------------------------------------------------------------------------
// 1) BatchNorm batch statistics
// ---------------------------------------------------------------------------
__global__ void bn_stats_kernel(const float* __restrict__ x) {
    float s0 = 0.f, s1 = 0.f, s2 = 0.f, t0 = 0.f, t1 = 0.f, t2 = 0.f;
    for (int p = threadIdx.x; p < NQ; p += 1024) {
        float v0 = x[p * 3 + 0], v1 = x[p * 3 + 1], v2 = x[p * 3 + 2];
        s0 += v0; s1 += v1; s2 += v2;
        t0 += v0 * v0; t1 += v1 * v1; t2 += v2 * v2;
    }
#pragma unroll
    for (int o = 16; o; o >>= 1) {
        s0 += __shfl_xor_sync(0xffffffffu, s0, o);
        s1 += __shfl_xor_sync(0xffffffffu, s1, o);
        s2 += __shfl_xor_sync(0xffffffffu, s2, o);
        t0 += __shfl_xor_sync(0xffffffffu, t0, o);
        t1 += __shfl_xor_sync(0xffffffffu, t1, o);
        t2 += __shfl_xor_sync(0xffffffffu, t2, o);
    }
    __shared__ float red[32][6];
    int lane = threadIdx.x & 31, w = threadIdx.x >> 5;
    if (lane == 0) {
        red[w][0] = s0; red[w][1] = s1; red[w][2] = s2;
        red[w][3] = t0; red[w][4] = t1; red[w][5] = t2;
    }
    __syncthreads();
    if (threadIdx.x < 32) {
        float a0 = red[lane][0], a1 = red[lane][1], a2 = red[lane][2];
        float a3 = red[lane][3], a4 = red[lane][4], a5 = red[lane][5];
#pragma unroll
        for (int o = 16; o; o >>= 1) {
            a0 += __shfl_xor_sync(0xffffffffu, a0, o);
            a1 += __shfl_xor_sync(0xffffffffu, a1, o);
            a2 += __shfl_xor_sync(0xffffffffu, a2, o);
            a3 += __shfl_xor_sync(0xffffffffu, a3, o);
            a4 += __shfl_xor_sync(0xffffffffu, a4, o);
            a5 += __shfl_xor_sync(0xffffffffu, a5, o);
        }
        if (lane == 0) {
            const float inv = 1.0f / (float)NQ;
            float m0 = a0 * inv, m1 = a1 * inv, m2 = a2 * inv;
            g_stats[0] = m0; g_stats[1] = m1; g_stats[2] = m2;
            g_stats[4] = rsqrtf(a3 * inv - m0 * m0 + 1e-5f);
            g_stats[5] = rsqrtf(a4 * inv - m1 * m1 + 1e-5f);
            g_stats[6] = rsqrtf(a5 * inv - m2 * m2 + 1e-5f);
        }
    }
}

// ---------------------------------------------------------------------------
// 2) h0 = normalize(x) @ W_in + b_in   (fp32 + bf16 hi/lo planes)
// ---------------------------------------------------------------------------
__global__ void input_proj_kernel(const float* __restrict__ x,
                                  const float* __restrict__ W_in,
                                  const float* __restrict__ b_in,
                                  float* __restrict__ h_out,
                                  __nv_bfloat16* __restrict__ hb_out) {
    int idx = blockIdx.x * 256 + threadIdx.x;
    int p = idx >> 6, c = idx & 63;
    float acc = b_in[c];
#pragma unroll
    for (int f = 0; f < 3; f++) {
        float xn = (x[p * 3 + f] - g_stats[f]) * g_stats[4 + f];
        acc += xn * W_in[f * 64 + c];
    }
    h_out[idx] = acc;
    __nv_bfloat16 hi = __float2bfloat16(acc);
    hb_out[idx] = hi;
    hb_out[NQ * 64 + idx] = __float2bfloat16(acc - __bfloat162float(hi));
}

// ---------------------------------------------------------------------------
// staging: A region = 195 rows x 64ch bf16, hi+lo planes, XOR-swizzled rows.
// pos outside [0,NQ) zero-filled (time zero-padding).
// ---------------------------------------------------------------------------
__device__ __forceinline__ void stage_region(uint32_t sb, const __nv_bfloat16* hb,
                                             int pos_rb, int tid) {
    for (int u = tid; u < 1560; u += 256) {
        int r = u >> 3, c4 = u & 7;
        uint32_t dhi = sb + (r << 7) + ((c4 ^ (r & 7)) << 4);
        int pos = pos_rb + r;
        int ok = (unsigned)pos < (unsigned)NQ;
        const __nv_bfloat16* s = hb + (size_t)(ok ? pos : 0) * 64 + c4 * 8;
        cpa16z(dhi, s, ok);
        cpa16z(dhi + ARL, s + NQ * 64, ok);
    }
}
__device__ __forceinline__ void stage_B(uint32_t dst, const unsigned* w, int tid) {
#pragma unroll
    for (int i = 0; i < 6; i++) {
        int u = tid + (i << 8);           // 0..1535 (24KB)
        cpa16(dst + (u << 4), w + (u << 2));
    }
}

// A fragment address: logical 16B chunk ck of row r, +4*tig within
__device__ __forceinline__ uint32_t aaddr(uint32_t ar, int r, int ck, int tig) {
    return ar + (r << 7) + (((ck) ^ (r & 7)) << 4) + (tig << 2);
}

// K-GEMM (single bf16 term): 16 rows x 64 cols, d[j*4+e]
__device__ __forceinline__ void mmaK(float* d, uint32_t ar, int rb, uint32_t bB,
                                     int tig, int lane) {
#pragma unroll
    for (int e = 0; e < 32; e++) d[e] = 0.0f;
    int r0 = rb, r1 = rb + 8;
#pragma unroll
    for (int ks = 0; ks < 4; ks++) {
        unsigned a[4];
        a[0] = lds32u(aaddr(ar, r0, 2 * ks, tig));
        a[1] = lds32u(aaddr(ar, r1, 2 * ks, tig));
        a[2] = lds32u(aaddr(ar, r0, 2 * ks + 1, tig));
        a[3] = lds32u(aaddr(ar, r1, 2 * ks + 1, tig));
#pragma unroll
        for (int j = 0; j < 8; j++) {
            unsigned b0, b1;
            lds64u(b0, b1, bB + (((j << 2) + ks) << 8) + (lane << 3));
            mma16(&d[j << 2], a, b0, b1);
        }
    }
}

// V-GEMM (3-term bf16 split): d = AhiVhi + AloVhi + AhiVlo
__device__ __forceinline__ void mmaV(float* d, uint32_t arh, uint32_t arl, int rb,
                                     uint32_t bHi, uint32_t bLo, int tig, int lane) {
#pragma unroll
    for (int e = 0; e < 32; e++) d[e] = 0.0f;
    int r0 = rb, r1 = rb + 8;
#pragma unroll
    for (int ks = 0; ks < 4; ks++) {
        unsigned ah[4], al[4];
        ah[0] = lds32u(aaddr(arh, r0, 2 * ks, tig));
        ah[1] = lds32u(aaddr(arh, r1, 2 * ks, tig));
        ah[2] = lds32u(aaddr(arh, r0, 2 * ks + 1, tig));
        ah[3] = lds32u(aaddr(arh, r1, 2 * ks + 1, tig));
        al[0] = lds32u(aaddr(arl, r0, 2 * ks, tig));
        al[1] = lds32u(aaddr(arl, r1, 2 * ks, tig));
        al[2] = lds32u(aaddr(arl, r0, 2 * ks + 1, tig));
        al[3] = lds32u(aaddr(arl, r1, 2 * ks + 1, tig));
#pragma unroll
        for (int j = 0; j < 8; j++) {
            uint32_t fo = (((j << 2) + ks) << 8) + (lane << 3);
            unsigned bh0, bh1, bl0, bl1;
            lds64u(bh0, bh1, bHi + fo);
            lds64u(bl0, bl1, bLo + fo);
            float* dd = &d[j << 2];
            mma16(dd, ah, bh0, bh1);
            mma16(dd, al, bh0, bh1);
            mma16(dd, ah, bl0, bl1);
        }
    }
}

// ---------------------------------------------------------------------------
// 3) Fused attention layer. 256 threads = 8 warps; warp w owns query rows
//    16w..16w+15 end-to-end (Q, K, scores, softmax, V, apply, store).
//    Offset order regrouped by dt: {m=9..17 (dt 0), 0..8 (dt -1), 18..26 (dt 1)}
//    so one A-region staging serves 9 offsets. B double-buffered per offset.
// ---------------------------------------------------------------------------
__global__ __launch_bounds__(256, 2)
void attn_kernel(const float* __restrict__ h_in, const __nv_bfloat16* __restrict__ hb,
                 float* __restrict__ h_out, __nv_bfloat16* __restrict__ hbo,
                 const unsigned* __restrict__ wq_pb, const float* __restrict__ bq,
                 const unsigned* __restrict__ wkv_pb,
                 const float* __restrict__ bk, const float* __restrict__ bv) {
    extern __shared__ char smem[];
    const uint32_t sb = smem_u32(smem);
    const int tid  = threadIdx.x;
    const int lane = tid & 31;
    const int w    = tid >> 5;
    const int tig  = lane & 3;
    const int l4   = lane >> 2;

    const int bx    = blockIdx.x;
    const int tbase = bx << 7;
    const int a0    = (bx & 7) << 2;
    const int rbase = (w << 4) + l4;        // warp row base in tile

    // ---- prologue: region(dt=0), Wq -> BB1, B[m=9] -> BB0 ----
    stage_region(sb, hb, tbase - 33, tid);
    for (int u = tid; u < 512; u += 256)
        cpa16(sb + BB1 + (u << 4), wq_pb + (u << 2));
    stage_B(sb + BB0, wkv_pb + 9 * 6144, tid);
    CPA_COMMIT(); CPA_WAIT0();
    __syncthreads();

    // ---- Q projection (rows at region-local base 33) ----
    float q[32];
    mmaK(q, sb + ARH, 33 + rbase, sb + BB1, tig, lane);
#pragma unroll
    for (int j = 0; j < 8; j++) {
        float2 b2 = __ldg((const float2*)(bq + 8 * j) + tig);
        q[j * 4 + 0] += b2.x; q[j * 4 + 1] += b2.y;
        q[j * 4 + 2] += b2.x; q[j * 4 + 3] += b2.y;
    }

    // ---- spatial validity masks (2 rows per lane) ----
    unsigned vm[2];
#pragma unroll
    for (int rh = 0; rh < 2; rh++) {
        int r = rbase + 8 * rh;
        int ga = a0 + (r >> 5), gb = r & 31;
        bool aM = (ga > 0), aP = (ga < 31), bM = (gb > 0), bP = (gb < 31);
        unsigned v = 0;
#pragma unroll
        for (int m = 0; m < MOFF; m++) {
            int r9 = m % 9;
            int di = r9 / 3 - 1, dj = r9 % 3 - 1;
            bool ok = (di < 0 ? aM : (di > 0 ? aP : true)) &&
                      (dj < 0 ? bM : (dj > 0 ? bP : true));
            v |= ((unsigned)ok) << m;
        }
        vm[rh] = v;
    }

    float acc[32];
#pragma unroll
    for (int e = 0; e < 32; e++) acc[e] = 0.0f;
    float den[8];
#pragma unroll
    for (int t = 0; t < 8; t++) den[t] = 0.0f;

    // ---- 27-offset mainloop ----
#pragma unroll 1
    for (int i = 0; i < MOFF; i++) {
        int m = i + (i < 9 ? 9 : (i < 18 ? -9 : 0));
        CPA_WAIT0();
        __syncthreads();      // B[i] (+ region at boundaries) ready; prev buf free
        if (i < 26) {
            int mn = i + 1;
            mn += (mn < 9 ? 9 : (mn < 18 ? -9 : 0));
            stage_B(sb + ((i & 1) ? BB0 : BB1), wkv_pb + mn * 6144, tid);
            CPA_COMMIT();
        }
        const uint32_t bB = sb + ((i & 1) ? BB1 : BB0);
        int r9 = m % 9;
        int di = r9 / 3 - 1, dj = r9 % 3 - 1;
        int Ab = 33 + di * 32 + dj + rbase;

        float d[32];
        // K projection + scores
        mmaK(d, sb + ARH, Ab, bB, tig, lane);
        float sp[8];
#pragma unroll
        for (int t = 0; t < 8; t++) sp[t] = 0.0f;
#pragma unroll
        for (int j = 0; j < 8; j++) {
            float2 bk2 = __ldg((const float2*)(bk + m * 64 + 8 * j) + tig);
#pragma unroll
            for (int rh = 0; rh < 2; rh++) {
                float k0 = d[j * 4 + rh * 2 + 0] + bk2.x;
                float k1 = d[j * 4 + rh * 2 + 1] + bk2.y;
                sp[rh * 4 + (j >> 1)] += k0 * q[j * 4 + rh * 2 + 0]
                                       + k1 * q[j * 4 + rh * 2 + 1];
            }
        }
        float p[8];
#pragma unroll
        for (int t = 0; t < 8; t++) {
            float s = sp[t];
            s += __shfl_xor_sync(0xffffffffu, s, 1);
            s += __shfl_xor_sync(0xffffffffu, s, 2);
            bool ok = (vm[t >> 2] >> m) & 1u;
            float pv = __expf(ok ? s : -1e30f);
            p[t] = pv;
            den[t] += pv;
        }

        // V projection (3-term) + apply
        mmaV(d, sb + ARH, sb + ARL, Ab, bB + 8192u, bB + 16384u, tig, lane);
#pragma unroll
        for (int j = 0; j < 8; j++) {
            float2 bv2 = __ldg((const float2*)(bv + m * 64 + 8 * j) + tig);
#pragma unroll
            for (int rh = 0; rh < 2; rh++) {
                float pw = p[rh * 4 + (j >> 1)];
                acc[j * 4 + rh * 2 + 0] += pw * (d[j * 4 + rh * 2 + 0] + bv2.x);
                acc[j * 4 + rh * 2 + 1] += pw * (d[j * 4 + rh * 2 + 1] + bv2.y);
            }
        }

        // region switch for next dt group
        if (i == 8 || i == 17) {
            __syncthreads();          // all region reads complete
            int dt = (i == 8) ? -1 : 1;
            stage_region(sb, hb, tbase + dt * 1024 - 33, tid);
            CPA_COMMIT();
        }
    }

    // ---- epilogue: per-head normalize + residual + fp32/bf16 store ----
    float inv[8];
#pragma unroll
    for (int t = 0; t < 8; t++) inv[t] = 1.0f / den[t];
#pragma unroll
    for (int rh = 0; rh < 2; rh++) {
        int pos = tbase + rbase + 8 * rh;
        const float* rp = h_in + ((size_t)pos << 6);
        float* op = h_out + ((size_t)pos << 6);
#pragma unroll
        for (int j = 0; j < 8; j++) {
            int c = 8 * j + 2 * tig;
            float iv = inv[rh * 4 + (j >> 1)];
            float2 r = *(const float2*)(rp + c);
            float ox = acc[j * 4 + rh * 2 + 0] * iv + r.x;
            float oy = acc[j * 4 + rh * 2 + 1] * iv + r.y;
            float2 o; o.x = ox; o.y = oy;
            *(float2*)(op + c) = o;
            if (hbo) {
                __nv_bfloat162 hi2 = __floats2bfloat162_rn(ox, oy);
                __nv_bfloat162 lo2 = __floats2bfloat162_rn(
                    ox - __bfloat162float(hi2.x), oy - __bfloat162float(hi2.y));
                *(unsigned*)(&hbo[(size_t)pos * 64 + c]) = *(unsigned*)&hi2;
                *(unsigned*)(&hbo[(size_t)(NQ + pos) * 64 + c]) = *(unsigned*)&lo2;
            }
        }
    }
}

// ---------------------------------------------------------------------------
// 4) out = h @ W_out + b_out
// ---------------------------------------------------------------------------
__global__ void out_proj_kernel(const float* __restrict__ h,
                                const float* __restrict__ W_out,
                                const float* __restrict__ b_out,
                                float* __restrict__ out) {
    __shared__ float hs[32 * 64];
    int tid = threadIdx.x;              // 128 threads
    int base = blockIdx.x * 32;
    for (int j = tid; j < 2048; j += 128) hs[j] = h[base * 64 + j];
    __syncthreads();
    if (tid < 96) {
        int rr = tid / 3, f = tid - 3 * (tid / 3);
        float acc = b_out[f];
#pragma unroll 8
        for (int cp = 0; cp < 64; cp++)
            acc += hs[rr * 64 + cp] * W_out[cp * 3 + f];
        out[(base + rr) * 3 + f] = acc;
    }
}

// ---------------------------------------------------------------------------
extern "C" void kernel_launch(void* const* d_in, const int* in_sizes, int n_in,
                              void* d_out, int out_size) {
    const float* x     = (const float*)d_in[0];
    const float* W_in  = (const float*)d_in[1];
    const float* b_in  = (const float*)d_in[2];
    const float* W_out = (const float*)d_in[3];
    const float* b_out = (const float*)d_in[4];
    const float* Wq    = (const float*)d_in[5];
    const float* bq    = (const float*)d_in[6];
    const float* Wk    = (const float*)d_in[7];
    const float* bk    = (const float*)d_in[8];
    const float* Wv    = (const float*)d_in[9];
    const float* bv    = (const float*)d_in[10];
    float* out = (float*)d_out;

    float *h0, *h1;
    __nv_bfloat16 *hbA, *hbB;
    unsigned *wq_pb, *wkv_pb;
    cudaGetSymbolAddress((void**)&h0, g_h0);
    cudaGetSymbolAddress((void**)&h1, g_h1);
    cudaGetSymbolAddress((void**)&hbA, g_hbA);
    cudaGetSymbolAddress((void**)&hbB, g_hbB);
    cudaGetSymbolAddress((void**)&wq_pb, g_wq_pb);
    cudaGetSymbolAddress((void**)&wkv_pb, g_wkv_pb);
    cudaFuncSetAttribute(attn_kernel, cudaFuncAttributeMaxDynamicSharedMemorySize, SMEMB);

    repack_w_kernel<<<(54 * 2048 + 255) / 256, 256>>>(Wq, Wk, Wv);
    bn_stats_kernel<<<1, 1024>>>(x);
    input_proj_kernel<<<(NQ * 64) / 256, 256>>>(x, W_in, b_in, h0, hbA);

    // layer 0: h0/hbA -> h1/hbB
    attn_kernel<<<256, 256, SMEMB>>>(h0, hbA, h1, hbB,
        wq_pb, bq, wkv_pb, bk, bv);
    // layer 1: h1/hbB -> h0 (no bf16 planes needed)
    attn_kernel<<<256, 256, SMEMB>>>(h1, hbB, h0, (__nv_bfloat16*)nullptr,
        wq_pb + 2048, bq + 64, wkv_pb + 27 * 6144, bk + 27 * 64, bv + 27 * 64);

    out_proj_kernel<<<NQ / 32, 128>>>(h0, W_out, b_out, out);
}

// round 8
// speedup vs baseline: 5.7409x; 1.0015x over previous
#include <cuda_runtime.h>
#include <cuda_bf16.h>
#include <math.h>
#include <stdint.h>

#define NQ   32768
#define MOFF 27

// smem byte offsets: A region hi/lo (195 rows x 128B each) + 2 B buffers (24KB)
#define ARH  0
#define ARL  24960
#define BB0  49920
#define BB1  74496
#define SMEMB 99072

// Scratch (static device globals: allocation-free per harness rules)
__device__ float g_h0[NQ * 64];
__device__ float g_h1[NQ * 64];
__device__ __nv_bfloat16 g_hbA[2 * NQ * 64];   // [hi plane | lo plane]
__device__ __nv_bfloat16 g_hbB[2 * NQ * 64];
__device__ float g_stats[8];
__device__ unsigned g_wq_pb[2 * 2048];         // frag-packed bf16 Wq^T per layer
__device__ unsigned g_wkv_pb[54 * 6144];       // per (layer,m): [Khi|Vhi|Vlo] 2048 u32 each

// ---------------------------------------------------------------------------
// helpers
// ---------------------------------------------------------------------------
__device__ __forceinline__ uint32_t smem_u32(const void* p) {
    uint32_t a;
    asm("{ .reg .u64 t; cvta.to.shared.u64 t, %1; cvt.u32.u64 %0, t; }" : "=r"(a) : "l"(p));
    return a;
}
__device__ __forceinline__ void cpa16z(uint32_t dst, const void* src, int ok) {
    asm volatile("cp.async.cg.shared.global [%0], [%1], 16, %2;"
                 :: "r"(dst), "l"(src), "r"(ok ? 16 : 0));
}
__device__ __forceinline__ void cpa16(uint32_t dst, const void* src) {
    asm volatile("cp.async.cg.shared.global [%0], [%1], 16;" :: "r"(dst), "l"(src));
}
#define CPA_COMMIT() asm volatile("cp.async.commit_group;" ::: "memory")
#define CPA_WAIT0()  asm volatile("cp.async.wait_group 0;"  ::: "memory")

__device__ __forceinline__ unsigned lds32u(uint32_t a) {
    unsigned v; asm volatile("ld.shared.b32 %0, [%1];" : "=r"(v) : "r"(a)); return v;
}
__device__ __forceinline__ void lds64u(unsigned& x, unsigned& y, uint32_t a) {
    asm volatile("ld.shared.v2.b32 {%0, %1}, [%2];" : "=r"(x), "=r"(y) : "r"(a));
}
// bf16 tensor-core mma (sm_80+ baseline PTX): D(16x8,f32) += A(16x16) * B(16x8)
__device__ __forceinline__ void mma16(float* d, const unsigned* a, unsigned b0, unsigned b1) {
    asm volatile(
        "mma.sync.aligned.m16n8k16.row.col.f32.bf16.bf16.f32 "
        "{%0,%1,%2,%3}, {%4,%5,%6,%7}, {%8,%9}, {%0,%1,%2,%3};"
        : "+f"(d[0]), "+f"(d[1]), "+f"(d[2]), "+f"(d[3])
        : "r"(a[0]), "r"(a[1]), "r"(a[2]), "r"(a[3]), "r"(b0), "r"(b1));
}
__device__ __forceinline__ unsigned packbf2(float x, float y) {
    __nv_bfloat162 t = __floats2bfloat162_rn(x, y);
    return *reinterpret_cast<unsigned*>(&t);
}
__device__ __forceinline__ float2 unpackbf2(unsigned u) {
    __nv_bfloat162 t = *reinterpret_cast<__nv_bfloat162*>(&u);
    return __bfloat1622float2(t);
}

// ---------------------------------------------------------------------------
// 0) Weight repack: per-lane m16n8k16 bf16 fragment order.
// ---------------------------------------------------------------------------
__global__ void repack_w_kernel(const float* __restrict__ Wq,
                                const float* __restrict__ Wk,
                                const float* __restrict__ Wv) {
    int idx = blockIdx.x * 256 + threadIdx.x;
    if (idx >= 54 * 2048) return;
    int mi = idx >> 11, e = idx & 2047;
    int fp = e >> 6, r = e & 63;
    int l = r >> 1, b = r & 1;
    int ks = fp & 3, j = fp >> 2;
    int cin  = 16 * ks + 2 * (l & 3) + 8 * b;
    int cout = 8 * j + (l >> 2);
    int s0 = mi * 4096 + cin * 64 + cout;
    g_wkv_pb[mi * 6144 + e] = packbf2(Wk[s0], Wk[s0 + 64]);
    float v0 = Wv[s0], v1 = Wv[s0 + 64];
    __nv_bfloat162 vh = __floats2bfloat162_rn(v0, v1);
    g_wkv_pb[mi * 6144 + 2048 + e] = *reinterpret_cast<unsigned*>(&vh);
    g_wkv_pb[mi * 6144 + 4096 + e] =
        packbf2(v0 - __bfloat162float(vh.x), v1 - __bfloat162float(vh.y));
    if (mi < 2)
        g_wq_pb[mi * 2048 + e] = packbf2(Wq[s0], Wq[s0 + 64]);
}

// ---------------------------------------------------------------------------
// 1) BatchNorm batch statistics
// ---------------------------------------------------------------------------
__global__ void bn_stats_kernel(const float* __restrict__ x) {
    float s0 = 0.f, s1 = 0.f, s2 = 0.f, t0 = 0.f, t1 = 0.f, t2 = 0.f;
    for (int p = threadIdx.x; p < NQ; p += 1024) {
        float v0 = x[p * 3 + 0], v1 = x[p * 3 + 1], v2 = x[p * 3 + 2];
        s0 += v0; s1 += v1; s2 += v2;
        t0 += v0 * v0; t1 += v1 * v1; t2 += v2 * v2;
    }
#pragma unroll
    for (int o = 16; o; o >>= 1) {
        s0 += __shfl_xor_sync(0xffffffffu, s0, o);
        s1 += __shfl_xor_sync(0xffffffffu, s1, o);
        s2 += __shfl_xor_sync(0xffffffffu, s2, o);
        t0 += __shfl_xor_sync(0xffffffffu, t0, o);
        t1 += __shfl_xor_sync(0xffffffffu, t1, o);
        t2 += __shfl_xor_sync(0xffffffffu, t2, o);
    }
    __shared__ float red[32][6];
    int lane = threadIdx.x & 31, w = threadIdx.x >> 5;
    if (lane == 0) {
        red[w][0] = s0; red[w][1] = s1; red[w][2] = s2;
        red[w][3] = t0; red[w][4] = t1; red[w][5] = t2;
    }
    __syncthreads();
    if (threadIdx.x < 32) {
        float a0 = red[lane][0], a1 = red[lane][1], a2 = red[lane][2];
        float a3 = red[lane][3], a4 = red[lane][4], a5 = red[lane][5];
#pragma unroll
        for (int o = 16; o; o >>= 1) {
            a0 += __shfl_xor_sync(0xffffffffu, a0, o);
            a1 += __shfl_xor_sync(0xffffffffu, a1, o);
            a2 += __shfl_xor_sync(0xffffffffu, a2, o);
            a3 += __shfl_xor_sync(0xffffffffu, a3, o);
            a4 += __shfl_xor_sync(0xffffffffu, a4, o);
            a5 += __shfl_xor_sync(0xffffffffu, a5, o);
        }
        if (lane == 0) {
            const float inv = 1.0f / (float)NQ;
            float m0 = a0 * inv, m1 = a1 * inv, m2 = a2 * inv;
            g_stats[0] = m0; g_stats[1] = m1; g_stats[2] = m2;
            g_stats[4] = rsqrtf(a3 * inv - m0 * m0 + 1e-5f);
            g_stats[5] = rsqrtf(a4 * inv - m1 * m1 + 1e-5f);
            g_stats[6] = rsqrtf(a5 * inv - m2 * m2 + 1e-5f);
        }
    }
}

// ---------------------------------------------------------------------------
// 2) h0 = normalize(x) @ W_in + b_in   (fp32 + bf16 hi/lo planes)
// ---------------------------------------------------------------------------
__global__ void input_proj_kernel(const float* __restrict__ x,
                                  const float* __restrict__ W_in,
                                  const float* __restrict__ b_in,
                                  float* __restrict__ h_out,
                                  __nv_bfloat16* __restrict__ hb_out) {
    int idx = blockIdx.x * 256 + threadIdx.x;
    int p = idx >> 6, c = idx & 63;
    float acc = b_in[c];
#pragma unroll
    for (int f = 0; f < 3; f++) {
        float xn = (x[p * 3 + f] - g_stats[f]) * g_stats[4 + f];
        acc += xn * W_in[f * 64 + c];
    }
    h_out[idx] = acc;
    __nv_bfloat16 hi = __float2bfloat16(acc);
    hb_out[idx] = hi;
    hb_out[NQ * 64 + idx] = __float2bfloat16(acc - __bfloat162float(hi));
}

// ---------------------------------------------------------------------------
// staging
// ---------------------------------------------------------------------------
__device__ __forceinline__ void stage_region(uint32_t sb, const __nv_bfloat16* hb,
                                             int pos_rb, int tid) {
    for (int u = tid; u < 1560; u += 256) {
        int r = u >> 3, c4 = u & 7;
        uint32_t dhi = sb + (r << 7) + ((c4 ^ (r & 7)) << 4);
        int pos = pos_rb + r;
        int ok = (unsigned)pos < (unsigned)NQ;
        const __nv_bfloat16* s = hb + (size_t)(ok ? pos : 0) * 64 + c4 * 8;
        cpa16z(dhi, s, ok);
        cpa16z(dhi + ARL, s + NQ * 64, ok);
    }
}
__device__ __forceinline__ void stage_B(uint32_t dst, const unsigned* w, int tid) {
#pragma unroll
    for (int i = 0; i < 6; i++) {
        int u = tid + (i << 8);
        cpa16(dst + (u << 4), w + (u << 2));
    }
}

__device__ __forceinline__ uint32_t aaddr(uint32_t ar, int r, int ck, int tig) {
    return ar + (r << 7) + (((ck) ^ (r & 7)) << 4) + (tig << 2);
}

// K-GEMM (single bf16 term): 16 rows x 64 cols, d[j*4+e]
__device__ __forceinline__ void mmaK(float* d, uint32_t ar, int rb, uint32_t bB,
                                     int tig, int lane) {
#pragma unroll
    for (int e = 0; e < 32; e++) d[e] = 0.0f;
    int r0 = rb, r1 = rb + 8;
#pragma unroll
    for (int ks = 0; ks < 4; ks++) {
        unsigned a[4];
        a[0] = lds32u(aaddr(ar, r0, 2 * ks, tig));
        a[1] = lds32u(aaddr(ar, r1, 2 * ks, tig));
        a[2] = lds32u(aaddr(ar, r0, 2 * ks + 1, tig));
        a[3] = lds32u(aaddr(ar, r1, 2 * ks + 1, tig));
#pragma unroll
        for (int j = 0; j < 8; j++) {
            unsigned b0, b1;
            lds64u(b0, b1, bB + (((j << 2) + ks) << 8) + (lane << 3));
            mma16(&d[j << 2], a, b0, b1);
        }
    }
}

// V-GEMM half (j = jb..jb+3), 3-term bf16 split -> d[16]
__device__ __forceinline__ void mmaVh(float* d, uint32_t arh, uint32_t arl, int rb,
                                      uint32_t bHi, uint32_t bLo, int tig, int lane,
                                      int jb) {
#pragma unroll
    for (int e = 0; e < 16; e++) d[e] = 0.0f;
    int r0 = rb, r1 = rb + 8;
#pragma unroll
    for (int ks = 0; ks < 4; ks++) {
        unsigned ah[4], al[4];
        ah[0] = lds32u(aaddr(arh, r0, 2 * ks, tig));
        ah[1] = lds32u(aaddr(arh, r1, 2 * ks, tig));
        ah[2] = lds32u(aaddr(arh, r0, 2 * ks + 1, tig));
        ah[3] = lds32u(aaddr(arh, r1, 2 * ks + 1, tig));
        al[0] = lds32u(aaddr(arl, r0, 2 * ks, tig));
        al[1] = lds32u(aaddr(arl, r1, 2 * ks, tig));
        al[2] = lds32u(aaddr(arl, r0, 2 * ks + 1, tig));
        al[3] = lds32u(aaddr(arl, r1, 2 * ks + 1, tig));
#pragma unroll
        for (int j = 0; j < 4; j++) {
            uint32_t fo = ((((jb + j) << 2) + ks) << 8) + (lane << 3);
            unsigned bh0, bh1, bl0, bl1;
            lds64u(bh0, bh1, bHi + fo);
            lds64u(bl0, bl1, bLo + fo);
            float* dd = &d[j << 2];
            mma16(dd, ah, bh0, bh1);
            mma16(dd, al, bh0, bh1);
            mma16(dd, ah, bl0, bl1);
        }
    }
}

// ---------------------------------------------------------------------------
// 3) Fused attention layer. 8 warps; warp w owns query rows 16w..16w+15.
//    q kept bf16-packed (16 regs); V done in two j-halves with fused apply.
// ---------------------------------------------------------------------------
__global__ __launch_bounds__(256, 2)
void attn_kernel(const float* __restrict__ h_in, const __nv_bfloat16* __restrict__ hb,
                 float* __restrict__ h_out, __nv_bfloat16* __restrict__ hbo,
                 const unsigned* __restrict__ wq_pb, const float* __restrict__ bq,
                 const unsigned* __restrict__ wkv_pb,
                 const float* __restrict__ bk, const float* __restrict__ bv) {
    extern __shared__ char smem[];
    const uint32_t sb = smem_u32(smem);
    const int tid  = threadIdx.x;
    const int lane = tid & 31;
    const int w    = tid >> 5;
    const int tig  = lane & 3;
    const int l4   = lane >> 2;

    const int bx    = blockIdx.x;
    const int tbase = bx << 7;
    const int a0    = (bx & 7) << 2;
    const int rbase = (w << 4) + l4;

    // ---- prologue: region(dt=0), Wq -> BB1, B[m=9] -> BB0 ----
    stage_region(sb, hb, tbase - 33, tid);
    for (int u = tid; u < 512; u += 256)
        cpa16(sb + BB1 + (u << 4), wq_pb + (u << 2));
    stage_B(sb + BB0, wkv_pb + 9 * 6144, tid);
    CPA_COMMIT(); CPA_WAIT0();
    __syncthreads();

    // ---- Q projection, packed to bf16 pairs ----
    unsigned qp[16];
    {
        float q[32];
        mmaK(q, sb + ARH, 33 + rbase, sb + BB1, tig, lane);
#pragma unroll
        for (int j = 0; j < 8; j++) {
            float2 b2 = __ldg((const float2*)(bq + 8 * j) + tig);
            qp[j * 2 + 0] = packbf2(q[j * 4 + 0] + b2.x, q[j * 4 + 1] + b2.y);
            qp[j * 2 + 1] = packbf2(q[j * 4 + 2] + b2.x, q[j * 4 + 3] + b2.y);
        }
    }

    // ---- spatial validity masks ----
    unsigned vm[2];
#pragma unroll
    for (int rh = 0; rh < 2; rh++) {
        int r = rbase + 8 * rh;
        int ga = a0 + (r >> 5), gb = r & 31;
        bool aM = (ga > 0), aP = (ga < 31), bM = (gb > 0), bP = (gb < 31);
        unsigned v = 0;
#pragma unroll
        for (int m = 0; m < MOFF; m++) {
            int r9 = m % 9;
            int di = r9 / 3 - 1, dj = r9 % 3 - 1;
            bool ok = (di < 0 ? aM : (di > 0 ? aP : true)) &&
                      (dj < 0 ? bM : (dj > 0 ? bP : true));
            v |= ((unsigned)ok) << m;
        }
        vm[rh] = v;
    }

    float acc[32];
#pragma unroll
    for (int e = 0; e < 32; e++) acc[e] = 0.0f;
    float den[8];
#pragma unroll
    for (int t = 0; t < 8; t++) den[t] = 0.0f;

    // ---- 27-offset mainloop ----
#pragma unroll 1
    for (int i = 0; i < MOFF; i++) {
        int m = i + (i < 9 ? 9 : (i < 18 ? -9 : 0));
        CPA_WAIT0();
        __syncthreads();
        if (i < 26) {
            int mn = i + 1;
            mn += (mn < 9 ? 9 : (mn < 18 ? -9 : 0));
            stage_B(sb + ((i & 1) ? BB0 : BB1), wkv_pb + mn * 6144, tid);
            CPA_COMMIT();
        }
        const uint32_t bB = sb + ((i & 1) ? BB1 : BB0);
        int r9 = m % 9;
        int di = r9 / 3 - 1, dj = r9 % 3 - 1;
        int Ab = 33 + di * 32 + dj + rbase;

        float p[8];
        {
            float d[32];
            mmaK(d, sb + ARH, Ab, bB, tig, lane);
            float sp[8];
#pragma unroll
            for (int t = 0; t < 8; t++) sp[t] = 0.0f;
#pragma unroll
            for (int j = 0; j < 8; j++) {
                float2 bk2 = __ldg((const float2*)(bk + m * 64 + 8 * j) + tig);
#pragma unroll
                for (int rh = 0; rh < 2; rh++) {
                    float2 qv = unpackbf2(qp[j * 2 + rh]);
                    float k0 = d[j * 4 + rh * 2 + 0] + bk2.x;
                    float k1 = d[j * 4 + rh * 2 + 1] + bk2.y;
                    sp[rh * 4 + (j >> 1)] += k0 * qv.x + k1 * qv.y;
                }
            }
#pragma unroll
            for (int t = 0; t < 8; t++) {
                float s = sp[t];
                s += __shfl_xor_sync(0xffffffffu, s, 1);
                s += __shfl_xor_sync(0xffffffffu, s, 2);
                bool ok = (vm[t >> 2] >> m) & 1u;
                float pv = __expf(ok ? s : -1e30f);
                p[t] = pv;
                den[t] += pv;
            }
        }

        // V projection in two j-halves with fused apply
#pragma unroll
        for (int jb = 0; jb < 8; jb += 4) {
            float d[16];
            mmaVh(d, sb + ARH, sb + ARL, Ab, bB + 8192u, bB + 16384u,
                  tig, lane, jb);
#pragma unroll
            for (int j = 0; j < 4; j++) {
                int jj = jb + j;
                float2 bv2 = __ldg((const float2*)(bv + m * 64 + 8 * jj) + tig);
#pragma unroll
                for (int rh = 0; rh < 2; rh++) {
                    float pw = p[rh * 4 + (jj >> 1)];
                    acc[jj * 4 + rh * 2 + 0] += pw * (d[j * 4 + rh * 2 + 0] + bv2.x);
                    acc[jj * 4 + rh * 2 + 1] += pw * (d[j * 4 + rh * 2 + 1] + bv2.y);
                }
            }
        }

        if (i == 8 || i == 17) {
            __syncthreads();
            int dt = (i == 8) ? -1 : 1;
            stage_region(sb, hb, tbase + dt * 1024 - 33, tid);
            CPA_COMMIT();
        }
    }

    // ---- epilogue ----
    float inv[8];
#pragma unroll
    for (int t = 0; t < 8; t++) inv[t] = 1.0f / den[t];
#pragma unroll
    for (int rh = 0; rh < 2; rh++) {
        int pos = tbase + rbase + 8 * rh;
        const float* rp = h_in + ((size_t)pos << 6);
        float* op = h_out + ((size_t)pos << 6);
#pragma unroll
        for (int j = 0; j < 8; j++) {
            int c = 8 * j + 2 * tig;
            float iv = inv[rh * 4 + (j >> 1)];
            float2 r = *(const float2*)(rp + c);
            float ox = acc[j * 4 + rh * 2 + 0] * iv + r.x;
            float oy = acc[j * 4 + rh * 2 + 1] * iv + r.y;
            float2 o; o.x = ox; o.y = oy;
            *(float2*)(op + c) = o;
            if (hbo) {
                __nv_bfloat162 hi2 = __floats2bfloat162_rn(ox, oy);
                __nv_bfloat162 lo2 = __floats2bfloat162_rn(
                    ox - __bfloat162float(hi2.x), oy - __bfloat162float(hi2.y));
                *(unsigned*)(&hbo[(size_t)pos * 64 + c]) = *(unsigned*)&hi2;
                *(unsigned*)(&hbo[(size_t)(NQ + pos) * 64 + c]) = *(unsigned*)&lo2;
            }
        }
    }
}

// ---------------------------------------------------------------------------
// 4) out = h @ W_out + b_out
// ---------------------------------------------------------------------------
__global__ void out_proj_kernel(const float* __restrict__ h,
                                const float* __restrict__ W_out,
                                const float* __restrict__ b_out,
                                float* __restrict__ out) {
    __shared__ float hs[32 * 64];
    int tid = threadIdx.x;
    int base = blockIdx.x * 32;
    for (int j = tid; j < 2048; j += 128) hs[j] = h[base * 64 + j];
    __syncthreads();
    if (tid < 96) {
        int rr = tid / 3, f = tid - 3 * (tid / 3);
        float acc = b_out[f];
#pragma unroll 8
        for (int cp = 0; cp < 64; cp++)
            acc += hs[rr * 64 + cp] * W_out[cp * 3 + f];
        out[(base + rr) * 3 + f] = acc;
    }
}

// ---------------------------------------------------------------------------
extern "C" void kernel_launch(void* const* d_in, const int* in_sizes, int n_in,
                              void* d_out, int out_size) {
    const float* x     = (const float*)d_in[0];
    const float* W_in  = (const float*)d_in[1];
    const float* b_in  = (const float*)d_in[2];
    const float* W_out = (const float*)d_in[3];
    const float* b_out = (const float*)d_in[4];
    const float* Wq    = (const float*)d_in[5];
    const float* bq    = (const float*)d_in[6];
    const float* Wk    = (const float*)d_in[7];
    const float* bk    = (const float*)d_in[8];
    const float* Wv    = (const float*)d_in[9];
    const float* bv    = (const float*)d_in[10];
    float* out = (float*)d_out;

    float *h0, *h1;
    __nv_bfloat16 *hbA, *hbB;
    unsigned *wq_pb, *wkv_pb;
    cudaGetSymbolAddress((void**)&h0, g_h0);
    cudaGetSymbolAddress((void**)&h1, g_h1);
    cudaGetSymbolAddress((void**)&hbA, g_hbA);
    cudaGetSymbolAddress((void**)&hbB, g_hbB);
    cudaGetSymbolAddress((void**)&wq_pb, g_wq_pb);
    cudaGetSymbolAddress((void**)&wkv_pb, g_wkv_pb);
    cudaFuncSetAttribute(attn_kernel, cudaFuncAttributeMaxDynamicSharedMemorySize, SMEMB);

    repack_w_kernel<<<(54 * 2048 + 255) / 256, 256>>>(Wq, Wk, Wv);
    bn_stats_kernel<<<1, 1024>>>(x);
    input_proj_kernel<<<(NQ * 64) / 256, 256>>>(x, W_in, b_in, h0, hbA);

    attn_kernel<<<256, 256, SMEMB>>>(h0, hbA, h1, hbB,
        wq_pb, bq, wkv_pb, bk, bv);
    attn_kernel<<<256, 256, SMEMB>>>(h1, hbB, h0, (__nv_bfloat16*)nullptr,
        wq_pb + 2048, bq + 64, wkv_pb + 27 * 6144, bk + 27 * 64, bv + 27 * 64);

    out_proj_kernel<<<NQ / 32, 128>>>(h0, W_out, b_out, out);
}

// round 9
// speedup vs baseline: 6.0965x; 1.0619x over previous
#include <cuda_runtime.h>
#include <cuda_fp16.h>
#include <math.h>
#include <stdint.h>

#define NQ   32768
#define MOFF 27

// smem: A region (195 rows x 128B fp16) + 2 B buffers (24KB each)
#define ARH  0
#define BB0  24960
#define BB1  49536
#define SMEMB 74112

// Scratch (static device globals: allocation-free per harness rules)
__device__ float g_h0[NQ * 64];
__device__ float g_h1[NQ * 64];
__device__ __half g_hf0[NQ * 64];            // fp16 image of h0
__device__ __half g_hf1[NQ * 64];
__device__ float g_stats[8];
__device__ unsigned g_wq_ph[2 * 2048];       // frag-packed fp16 Wq^T per layer
__device__ unsigned g_wkv_ph[54 * 6144];     // per (layer,m): [Khi|Vhi|Vlo] 2048 u32 each

// ---------------------------------------------------------------------------
__device__ __forceinline__ uint32_t smem_u32(const void* p) {
    uint32_t a;
    asm("{ .reg .u64 t; cvta.to.shared.u64 t, %1; cvt.u32.u64 %0, t; }" : "=r"(a) : "l"(p));
    return a;
}
__device__ __forceinline__ void cpa16z(uint32_t dst, const void* src, int ok) {
    asm volatile("cp.async.cg.shared.global [%0], [%1], 16, %2;"
                 :: "r"(dst), "l"(src), "r"(ok ? 16 : 0));
}
__device__ __forceinline__ void cpa16(uint32_t dst, const void* src) {
    asm volatile("cp.async.cg.shared.global [%0], [%1], 16;" :: "r"(dst), "l"(src));
}
#define CPA_COMMIT() asm volatile("cp.async.commit_group;" ::: "memory")
#define CPA_WAIT0()  asm volatile("cp.async.wait_group 0;"  ::: "memory")

__device__ __forceinline__ unsigned lds32u(uint32_t a) {
    unsigned v; asm volatile("ld.shared.b32 %0, [%1];" : "=r"(v) : "r"(a)); return v;
}
__device__ __forceinline__ void lds64u(unsigned& x, unsigned& y, uint32_t a) {
    asm volatile("ld.shared.v2.b32 {%0, %1}, [%2];" : "=r"(x), "=r"(y) : "r"(a));
}
// fp16 tensor-core mma (sm_80+ baseline PTX): D(16x8,f32) += A(16x16) * B(16x8)
__device__ __forceinline__ void mma16(float* d, const unsigned* a, unsigned b0, unsigned b1) {
    asm volatile(
        "mma.sync.aligned.m16n8k16.row.col.f32.f16.f16.f32 "
        "{%0,%1,%2,%3}, {%4,%5,%6,%7}, {%8,%9}, {%0,%1,%2,%3};"
        : "+f"(d[0]), "+f"(d[1]), "+f"(d[2]), "+f"(d[3])
        : "r"(a[0]), "r"(a[1]), "r"(a[2]), "r"(a[3]), "r"(b0), "r"(b1));
}
__device__ __forceinline__ unsigned packh2(float x, float y) {
    __half2 t = __floats2half2_rn(x, y);
    return *reinterpret_cast<unsigned*>(&t);
}
__device__ __forceinline__ float2 unpackh2(unsigned u) {
    __half2 t = *reinterpret_cast<__half2*>(&u);
    return __half22float2(t);
}

// ---------------------------------------------------------------------------
// 0) Weight repack: per-lane m16n8k16 fp16 fragment order.
//    frag fp = j*4+ks; u32 r = l*2+b:  cin0 = 16ks + 2(l&3) + 8b,
//    cout = 8j + (l>>2); u32 = {W[cin0][cout], W[cin0+1][cout]}
//    Wv split into fp16 hi + lo planes.
// ---------------------------------------------------------------------------
__global__ void repack_w_kernel(const float* __restrict__ Wq,
                                const float* __restrict__ Wk,
                                const float* __restrict__ Wv) {
    int idx = blockIdx.x * 256 + threadIdx.x;
    if (idx >= 54 * 2048) return;
    int mi = idx >> 11, e = idx & 2047;
    int fp = e >> 6, r = e & 63;
    int l = r >> 1, b = r & 1;
    int ks = fp & 3, j = fp >> 2;
    int cin  = 16 * ks + 2 * (l & 3) + 8 * b;
    int cout = 8 * j + (l >> 2);
    int s0 = mi * 4096 + cin * 64 + cout;
    g_wkv_ph[mi * 6144 + e] = packh2(Wk[s0], Wk[s0 + 64]);
    float v0 = Wv[s0], v1 = Wv[s0 + 64];
    __half h0 = __float2half_rn(v0), h1 = __float2half_rn(v1);
    __half2 hh; hh.x = h0; hh.y = h1;
    g_wkv_ph[mi * 6144 + 2048 + e] = *reinterpret_cast<unsigned*>(&hh);
    g_wkv_ph[mi * 6144 + 4096 + e] =
        packh2(v0 - __half2float(h0), v1 - __half2float(h1));
    if (mi < 2)
        g_wq_ph[mi * 2048 + e] = packh2(Wq[s0], Wq[s0 + 64]);
}

// ---------------------------------------------------------------------------
// 1) BatchNorm batch statistics
// ---------------------------------------------------------------------------
__global__ void bn_stats_kernel(const float* __restrict__ x) {
    float s0 = 0.f, s1 = 0.f, s2 = 0.f, t0 = 0.f, t1 = 0.f, t2 = 0.f;
    for (int p = threadIdx.x; p < NQ; p += 1024) {
        float v0 = x[p * 3 + 0], v1 = x[p * 3 + 1], v2 = x[p * 3 + 2];
        s0 += v0; s1 += v1; s2 += v2;
        t0 += v0 * v0; t1 += v1 * v1; t2 += v2 * v2;
    }
#pragma unroll
    for (int o = 16; o; o >>= 1) {
        s0 += __shfl_xor_sync(0xffffffffu, s0, o);
        s1 += __shfl_xor_sync(0xffffffffu, s1, o);
        s2 += __shfl_xor_sync(0xffffffffu, s2, o);
        t0 += __shfl_xor_sync(0xffffffffu, t0, o);
        t1 += __shfl_xor_sync(0xffffffffu, t1, o);
        t2 += __shfl_xor_sync(0xffffffffu, t2, o);
    }
    __shared__ float red[32][6];
    int lane = threadIdx.x & 31, w = threadIdx.x >> 5;
    if (lane == 0) {
        red[w][0] = s0; red[w][1] = s1; red[w][2] = s2;
        red[w][3] = t0; red[w][4] = t1; red[w][5] = t2;
    }
    __syncthreads();
    if (threadIdx.x < 32) {
        float a0 = red[lane][0], a1 = red[lane][1], a2 = red[lane][2];
        float a3 = red[lane][3], a4 = red[lane][4], a5 = red[lane][5];
#pragma unroll
        for (int o = 16; o; o >>= 1) {
            a0 += __shfl_xor_sync(0xffffffffu, a0, o);
            a1 += __shfl_xor_sync(0xffffffffu, a1, o);
            a2 += __shfl_xor_sync(0xffffffffu, a2, o);
            a3 += __shfl_xor_sync(0xffffffffu, a3, o);
            a4 += __shfl_xor_sync(0xffffffffu, a4, o);
            a5 += __shfl_xor_sync(0xffffffffu, a5, o);
        }
        if (lane == 0) {
            const float inv = 1.0f / (float)NQ;
            float m0 = a0 * inv, m1 = a1 * inv, m2 = a2 * inv;
            g_stats[0] = m0; g_stats[1] = m1; g_stats[2] = m2;
            g_stats[4] = rsqrtf(a3 * inv - m0 * m0 + 1e-5f);
            g_stats[5] = rsqrtf(a4 * inv - m1 * m1 + 1e-5f);
            g_stats[6] = rsqrtf(a5 * inv - m2 * m2 + 1e-5f);
        }
    }
}

// ---------------------------------------------------------------------------
// 2) h0 = normalize(x) @ W_in + b_in   (fp32 + fp16 image)
// ---------------------------------------------------------------------------
__global__ void input_proj_kernel(const float* __restrict__ x,
                                  const float* __restrict__ W_in,
                                  const float* __restrict__ b_in,
                                  float* __restrict__ h_out,
                                  __half* __restrict__ hf_out) {
    int idx = blockIdx.x * 256 + threadIdx.x;
    int p = idx >> 6, c = idx & 63;
    float acc = b_in[c];
#pragma unroll
    for (int f = 0; f < 3; f++) {
        float xn = (x[p * 3 + f] - g_stats[f]) * g_stats[4 + f];
        acc += xn * W_in[f * 64 + c];
    }
    h_out[idx] = acc;
    hf_out[idx] = __float2half_rn(acc);
}

// ---------------------------------------------------------------------------
// staging
// ---------------------------------------------------------------------------
__device__ __forceinline__ void stage_region(uint32_t sb, const __half* hf,
                                             int pos_rb, int tid) {
    for (int u = tid; u < 1560; u += 256) {
        int r = u >> 3, c4 = u & 7;
        uint32_t dst = sb + (r << 7) + ((c4 ^ (r & 7)) << 4);
        int pos = pos_rb + r;
        int ok = (unsigned)pos < (unsigned)NQ;
        cpa16z(dst, hf + (size_t)(ok ? pos : 0) * 64 + c4 * 8, ok);
    }
}
__device__ __forceinline__ void stage_B(uint32_t dst, const unsigned* w, int tid) {
#pragma unroll
    for (int i = 0; i < 6; i++) {
        int u = tid + (i << 8);
        cpa16(dst + (u << 4), w + (u << 2));
    }
}
__device__ __forceinline__ uint32_t aaddr(uint32_t base, int r, int ck, int tig) {
    return base + (r << 7) + ((ck ^ (r & 7)) << 4) + (tig << 2);
}

// load A fragment for one m16 tile (rows r0, r0+8) at k-step ks
__device__ __forceinline__ void loadA(unsigned* a, uint32_t ab, int r0, int ks, int tig) {
    a[0] = lds32u(aaddr(ab, r0,     2 * ks,     tig));
    a[1] = lds32u(aaddr(ab, r0 + 8, 2 * ks,     tig));
    a[2] = lds32u(aaddr(ab, r0,     2 * ks + 1, tig));
    a[3] = lds32u(aaddr(ab, r0 + 8, 2 * ks + 1, tig));
}

// ---------------------------------------------------------------------------
// 3) Fused attention layer. 8 warps; warp tile = 64 query rows x 16 channels
//    (one head): rg = w&1 -> rows 64rg..64rg+63 (4 m16 tiles); cg = w>>1 ->
//    head cg, channels 16cg..16cg+15 (2 n8 tiles). B weights read once per
//    2 row-groups (4x less B traffic than 16-row warps); scores head-local.
// ---------------------------------------------------------------------------
__global__ __launch_bounds__(256, 2)
void attn_kernel(const float* __restrict__ h_in, const __half* __restrict__ hf,
                 float* __restrict__ h_out, __half* __restrict__ hfo,
                 const unsigned* __restrict__ wq_ph, const float* __restrict__ bq,
                 const unsigned* __restrict__ wkv_ph,
                 const float* __restrict__ bk, const float* __restrict__ bv) {
    extern __shared__ char smem[];
    const uint32_t sb = smem_u32(smem);
    const int tid  = threadIdx.x;
    const int lane = tid & 31;
    const int w    = tid >> 5;
    const int tig  = lane & 3;
    const int l4   = lane >> 2;
    const int rg   = w & 1;
    const int cg   = w >> 1;

    const int bx    = blockIdx.x;
    const int tbase = bx << 7;
    const int a0    = (bx & 7) << 2;
    const int rwarp = (rg << 6) + l4;     // + 16*mt (+8) for row within tile

    // ---- prologue: region(dt=0), Wq -> BB1, B[m=9] -> BB0 ----
    stage_region(sb, hf, tbase - 33, tid);
    for (int u = tid; u < 512; u += 256)
        cpa16(sb + BB1 + (u << 4), wq_ph + (u << 2));
    stage_B(sb + BB0, wkv_ph + 9 * 6144, tid);
    CPA_COMMIT(); CPA_WAIT0();
    __syncthreads();

    // ---- Q projection for warp tile; packed fp16 pairs qp[16] ----
    unsigned qp[16];
    {
        float qf[32];
#pragma unroll
        for (int e = 0; e < 32; e++) qf[e] = 0.0f;
#pragma unroll
        for (int ks = 0; ks < 4; ks++) {
            unsigned bqf[4];
#pragma unroll
            for (int j = 0; j < 2; j++)
                lds64u(bqf[j * 2], bqf[j * 2 + 1],
                       sb + BB1 + ((((2 * cg + j) << 2) + ks) << 8) + (lane << 3));
#pragma unroll
            for (int mt = 0; mt < 4; mt++) {
                unsigned a[4];
                loadA(a, sb + ARH, 33 + rwarp + (mt << 4), ks, tig);
                mma16(&qf[(mt * 2 + 0) * 4], a, bqf[0], bqf[1]);
                mma16(&qf[(mt * 2 + 1) * 4], a, bqf[2], bqf[3]);
            }
        }
#pragma unroll
        for (int mt = 0; mt < 4; mt++)
#pragma unroll
            for (int j = 0; j < 2; j++) {
                float2 b2 = __ldg((const float2*)(bq + 16 * cg + 8 * j) + tig);
#pragma unroll
                for (int rh = 0; rh < 2; rh++)
                    qp[(mt * 2 + j) * 2 + rh] =
                        packh2(qf[(mt * 2 + j) * 4 + rh * 2 + 0] + b2.x,
                               qf[(mt * 2 + j) * 4 + rh * 2 + 1] + b2.y);
            }
    }

    // ---- spatial validity masks for this lane's 8 rows ----
    unsigned vm[8];
#pragma unroll
    for (int t = 0; t < 8; t++) {
        int lr = rwarp + ((t >> 1) << 4) + ((t & 1) << 3);   // mt = t>>1, rh = t&1
        int ga = a0 + (lr >> 5), gb = lr & 31;
        bool aM = (ga > 0), aP = (ga < 31), bM = (gb > 0), bP = (gb < 31);
        unsigned v = 0;
#pragma unroll
        for (int m = 0; m < MOFF; m++) {
            int r9 = m % 9;
            int di = r9 / 3 - 1, dj = r9 % 3 - 1;
            bool ok = (di < 0 ? aM : (di > 0 ? aP : true)) &&
                      (dj < 0 ? bM : (dj > 0 ? bP : true));
            v |= ((unsigned)ok) << m;
        }
        vm[t] = v;
    }

    float acc[32], den[8];
#pragma unroll
    for (int e = 0; e < 32; e++) acc[e] = 0.0f;
#pragma unroll
    for (int t = 0; t < 8; t++) den[t] = 0.0f;

    // ---- 27-offset mainloop (dt-grouped: 9..17, 0..8, 18..26) ----
#pragma unroll 1
    for (int i = 0; i < MOFF; i++) {
        int m = i + (i < 9 ? 9 : (i < 18 ? -9 : 0));
        CPA_WAIT0();
        __syncthreads();
        if (i < 26) {
            int mn = i + 1;
            mn += (mn < 9 ? 9 : (mn < 18 ? -9 : 0));
            stage_B(sb + ((i & 1) ? BB0 : BB1), wkv_ph + mn * 6144, tid);
            CPA_COMMIT();
        }
        const uint32_t bB = sb + ((i & 1) ? BB1 : BB0);
        int r9 = m % 9;
        int di = r9 / 3 - 1, dj = r9 % 3 - 1;
        const int Ab = 33 + di * 32 + dj + rwarp;

        float p[8];
        {
            // K-pass
            float dK[32];
#pragma unroll
            for (int e = 0; e < 32; e++) dK[e] = 0.0f;
#pragma unroll
            for (int ks = 0; ks < 4; ks++) {
                unsigned bf[4];
#pragma unroll
                for (int j = 0; j < 2; j++)
                    lds64u(bf[j * 2], bf[j * 2 + 1],
                           bB + ((((2 * cg + j) << 2) + ks) << 8) + (lane << 3));
#pragma unroll
                for (int mt = 0; mt < 4; mt++) {
                    unsigned a[4];
                    loadA(a, sb + ARH, Ab + (mt << 4), ks, tig);
                    mma16(&dK[(mt * 2 + 0) * 4], a, bf[0], bf[1]);
                    mma16(&dK[(mt * 2 + 1) * 4], a, bf[2], bf[3]);
                }
            }
            // scores over this head's 16 channels
            float sp[8];
#pragma unroll
            for (int t = 0; t < 8; t++) sp[t] = 0.0f;
#pragma unroll
            for (int mt = 0; mt < 4; mt++)
#pragma unroll
                for (int j = 0; j < 2; j++) {
                    float2 bk2 = __ldg((const float2*)(bk + m * 64 + 16 * cg + 8 * j) + tig);
#pragma unroll
                    for (int rh = 0; rh < 2; rh++) {
                        float2 qv = unpackh2(qp[(mt * 2 + j) * 2 + rh]);
                        float k0 = dK[(mt * 2 + j) * 4 + rh * 2 + 0] + bk2.x;
                        float k1 = dK[(mt * 2 + j) * 4 + rh * 2 + 1] + bk2.y;
                        sp[mt * 2 + rh] += k0 * qv.x + k1 * qv.y;
                    }
                }
#pragma unroll
            for (int t = 0; t < 8; t++) {
                float s = sp[t];
                s += __shfl_xor_sync(0xffffffffu, s, 1);
                s += __shfl_xor_sync(0xffffffffu, s, 2);
                bool ok = (vm[t] >> m) & 1u;
                float pv = __expf(ok ? s : -1e30f);
                p[t] = pv;
                den[t] += pv;
            }
        }

        // V-pass (2-term fp16 split: Ahi*Vhi + Ahi*Vlo)
        {
            float dV[32];
#pragma unroll
            for (int e = 0; e < 32; e++) dV[e] = 0.0f;
#pragma unroll
            for (int ks = 0; ks < 4; ks++) {
                unsigned bh[4], bl[4];
#pragma unroll
                for (int j = 0; j < 2; j++) {
                    uint32_t fo = ((((2 * cg + j) << 2) + ks) << 8) + (lane << 3);
                    lds64u(bh[j * 2], bh[j * 2 + 1], bB + 8192u + fo);
                    lds64u(bl[j * 2], bl[j * 2 + 1], bB + 16384u + fo);
                }
#pragma unroll
                for (int mt = 0; mt < 4; mt++) {
                    unsigned a[4];
                    loadA(a, sb + ARH, Ab + (mt << 4), ks, tig);
                    mma16(&dV[(mt * 2 + 0) * 4], a, bh[0], bh[1]);
                    mma16(&dV[(mt * 2 + 0) * 4], a, bl[0], bl[1]);
                    mma16(&dV[(mt * 2 + 1) * 4], a, bh[2], bh[3]);
                    mma16(&dV[(mt * 2 + 1) * 4], a, bl[2], bl[3]);
                }
            }
#pragma unroll
            for (int mt = 0; mt < 4; mt++)
#pragma unroll
                for (int j = 0; j < 2; j++) {
                    float2 bv2 = __ldg((const float2*)(bv + m * 64 + 16 * cg + 8 * j) + tig);
#pragma unroll
                    for (int rh = 0; rh < 2; rh++) {
                        float pw = p[mt * 2 + rh];
                        acc[(mt * 2 + j) * 4 + rh * 2 + 0] +=
                            pw * (dV[(mt * 2 + j) * 4 + rh * 2 + 0] + bv2.x);
                        acc[(mt * 2 + j) * 4 + rh * 2 + 1] +=
                            pw * (dV[(mt * 2 + j) * 4 + rh * 2 + 1] + bv2.y);
                    }
                }
        }

        if (i == 8 || i == 17) {
            __syncthreads();
            int dt = (i == 8) ? -1 : 1;
            stage_region(sb, hf, tbase + dt * 1024 - 33, tid);
            CPA_COMMIT();
        }
    }

    // ---- epilogue: per-(row) head-normalize + residual + store ----
#pragma unroll
    for (int mt = 0; mt < 4; mt++)
#pragma unroll
        for (int rh = 0; rh < 2; rh++) {
            int pos = tbase + rwarp + (mt << 4) + (rh << 3);
            float iv = 1.0f / den[mt * 2 + rh];
            const float* rp = h_in + ((size_t)pos << 6);
            float* op = h_out + ((size_t)pos << 6);
#pragma unroll
            for (int j = 0; j < 2; j++) {
                int c = 16 * cg + 8 * j + 2 * tig;
                float2 r = *(const float2*)(rp + c);
                float ox = acc[(mt * 2 + j) * 4 + rh * 2 + 0] * iv + r.x;
                float oy = acc[(mt * 2 + j) * 4 + rh * 2 + 1] * iv + r.y;
                float2 o; o.x = ox; o.y = oy;
                *(float2*)(op + c) = o;
                if (hfo) {
                    __half2 h2 = __floats2half2_rn(ox, oy);
                    *(unsigned*)(&hfo[(size_t)pos * 64 + c]) = *(unsigned*)&h2;
                }
            }
        }
}

// ---------------------------------------------------------------------------
// 4) out = h @ W_out + b_out
// ---------------------------------------------------------------------------
__global__ void out_proj_kernel(const float* __restrict__ h,
                                const float* __restrict__ W_out,
                                const float* __restrict__ b_out,
                                float* __restrict__ out) {
    __shared__ float hs[32 * 64];
    int tid = threadIdx.x;
    int base = blockIdx.x * 32;
    for (int j = tid; j < 2048; j += 128) hs[j] = h[base * 64 + j];
    __syncthreads();
    if (tid < 96) {
        int rr = tid / 3, f = tid - 3 * (tid / 3);
        float acc = b_out[f];
#pragma unroll 8
        for (int cp = 0; cp < 64; cp++)
            acc += hs[rr * 64 + cp] * W_out[cp * 3 + f];
        out[(base + rr) * 3 + f] = acc;
    }
}

// ---------------------------------------------------------------------------
extern "C" void kernel_launch(void* const* d_in, const int* in_sizes, int n_in,
                              void* d_out, int out_size) {
    const float* x     = (const float*)d_in[0];
    const float* W_in  = (const float*)d_in[1];
    const float* b_in  = (const float*)d_in[2];
    const float* W_out = (const float*)d_in[3];
    const float* b_out = (const float*)d_in[4];
    const float* Wq    = (const float*)d_in[5];
    const float* bq    = (const float*)d_in[6];
    const float* Wk    = (const float*)d_in[7];
    const float* bk    = (const float*)d_in[8];
    const float* Wv    = (const float*)d_in[9];
    const float* bv    = (const float*)d_in[10];
    float* out = (float*)d_out;

    float *h0, *h1;
    __half *hf0, *hf1;
    unsigned *wq_ph, *wkv_ph;
    cudaGetSymbolAddress((void**)&h0, g_h0);
    cudaGetSymbolAddress((void**)&h1, g_h1);
    cudaGetSymbolAddress((void**)&hf0, g_hf0);
    cudaGetSymbolAddress((void**)&hf1, g_hf1);
    cudaGetSymbolAddress((void**)&wq_ph, g_wq_ph);
    cudaGetSymbolAddress((void**)&wkv_ph, g_wkv_ph);
    cudaFuncSetAttribute(attn_kernel, cudaFuncAttributeMaxDynamicSharedMemorySize, SMEMB);

    repack_w_kernel<<<(54 * 2048 + 255) / 256, 256>>>(Wq, Wk, Wv);
    bn_stats_kernel<<<1, 1024>>>(x);
    input_proj_kernel<<<(NQ * 64) / 256, 256>>>(x, W_in, b_in, h0, hf0);

    attn_kernel<<<256, 256, SMEMB>>>(h0, hf0, h1, hf1,
        wq_ph, bq, wkv_ph, bk, bv);
    attn_kernel<<<256, 256, SMEMB>>>(h1, hf1, h0, (__half*)nullptr,
        wq_ph + 2048, bq + 64, wkv_ph + 27 * 6144, bk + 27 * 64, bv + 27 * 64);

    out_proj_kernel<<<NQ / 32, 128>>>(h0, W_out, b_out, out);
}

// round 10
// speedup vs baseline: 8.3973x; 1.3774x over previous
#include <cuda_runtime.h>
#include <cuda_fp16.h>
#include <math.h>
#include <stdint.h>

#define NQ   32768
#define MOFF 27

// smem: A region (195 rows x 128B fp16) + 2 B buffers (16KB each: [K 8KB|V 8KB])
#define ARH  0
#define BB0  24960
#define BB1  41344
#define SMEMB 57728

// Scratch (static device globals: allocation-free per harness rules)
__device__ float g_h0[NQ * 64];
__device__ float g_h1[NQ * 64];
__device__ __half g_hf0[NQ * 64];
__device__ __half g_hf1[NQ * 64];
__device__ float g_stats[8];
__device__ unsigned g_wq_ph[2 * 2048];     // per layer: lds128-frag-packed fp16 Wq^T
__device__ unsigned g_wkv_ph[54 * 4096];   // per (layer,m): [K 2048 | V 2048] u32

// ---------------------------------------------------------------------------
__device__ __forceinline__ uint32_t smem_u32(const void* p) {
    uint32_t a;
    asm("{ .reg .u64 t; cvta.to.shared.u64 t, %1; cvt.u32.u64 %0, t; }" : "=r"(a) : "l"(p));
    return a;
}
__device__ __forceinline__ void cpa16z(uint32_t dst, const void* src, int ok) {
    asm volatile("cp.async.cg.shared.global [%0], [%1], 16, %2;"
                 :: "r"(dst), "l"(src), "r"(ok ? 16 : 0));
}
__device__ __forceinline__ void cpa16(uint32_t dst, const void* src) {
    asm volatile("cp.async.cg.shared.global [%0], [%1], 16;" :: "r"(dst), "l"(src));
}
#define CPA_COMMIT() asm volatile("cp.async.commit_group;" ::: "memory")
#define CPA_WAIT0()  asm volatile("cp.async.wait_group 0;"  ::: "memory")

__device__ __forceinline__ void lds128u(unsigned* v, uint32_t a) {
    asm volatile("ld.shared.v4.b32 {%0, %1, %2, %3}, [%4];"
                 : "=r"(v[0]), "=r"(v[1]), "=r"(v[2]), "=r"(v[3]) : "r"(a));
}
// ldmatrix x4 (sm_75+ baseline): 4 8x8 b16 matrices, per-lane row pointers
__device__ __forceinline__ void ldsm4(unsigned* r, uint32_t a) {
    asm volatile("ldmatrix.sync.aligned.m8n8.x4.shared.b16 {%0, %1, %2, %3}, [%4];"
                 : "=r"(r[0]), "=r"(r[1]), "=r"(r[2]), "=r"(r[3]) : "r"(a));
}
// fp16 tensor-core mma (sm_80+ baseline): D(16x8,f32) += A(16x16) * B(16x8)
__device__ __forceinline__ void mma16(float* d, const unsigned* a, unsigned b0, unsigned b1) {
    asm volatile(
        "mma.sync.aligned.m16n8k16.row.col.f32.f16.f16.f32 "
        "{%0,%1,%2,%3}, {%4,%5,%6,%7}, {%8,%9}, {%0,%1,%2,%3};"
        : "+f"(d[0]), "+f"(d[1]), "+f"(d[2]), "+f"(d[3])
        : "r"(a[0]), "r"(a[1]), "r"(a[2]), "r"(a[3]), "r"(b0), "r"(b1));
}
__device__ __forceinline__ unsigned packh2(float x, float y) {
    __half2 t = __floats2half2_rn(x, y);
    return *reinterpret_cast<unsigned*>(&t);
}
__device__ __forceinline__ float2 unpackh2(unsigned u) {
    __half2 t = *reinterpret_cast<__half2*>(&u);
    return __half22float2(t);
}

// ---------------------------------------------------------------------------
// 0) Weight repack to lds128 fragment layout:
//    u32 e = ((cg*4 + ks)*32 + lane)*4 + u, u in 0..3:
//      j = u>>1 (n8 tile within head), b = u&1 (k-half)
//      cin0 = 16ks + 2(lane&3) + 8b;  cout = 16cg + 8j + (lane>>2)
//      value = {W[cin0][cout], W[cin0+1][cout]} as fp16x2
// ---------------------------------------------------------------------------
__global__ void repack_w_kernel(const float* __restrict__ Wq,
                                const float* __restrict__ Wk,
                                const float* __restrict__ Wv) {
    int idx = blockIdx.x * 256 + threadIdx.x;
    if (idx >= 54 * 2048) return;
    int mi = idx >> 11, e = idx & 2047;
    int cg = e >> 9, ks = (e >> 7) & 3, lane = (e >> 2) & 31, u = e & 3;
    int cin  = 16 * ks + 2 * (lane & 3) + 8 * (u & 1);
    int cout = 16 * cg + 8 * (u >> 1) + (lane >> 2);
    int s0 = mi * 4096 + cin * 64 + cout;
    g_wkv_ph[mi * 4096 + e]        = packh2(Wk[s0], Wk[s0 + 64]);
    g_wkv_ph[mi * 4096 + 2048 + e] = packh2(Wv[s0], Wv[s0 + 64]);
    if (mi < 2)
        g_wq_ph[mi * 2048 + e] = packh2(Wq[s0], Wq[s0 + 64]);
}

// ---------------------------------------------------------------------------
// 1) BatchNorm batch statistics
// ---------------------------------------------------------------------------
__global__ void bn_stats_kernel(const float* __restrict__ x) {
    float s0 = 0.f, s1 = 0.f, s2 = 0.f, t0 = 0.f, t1 = 0.f, t2 = 0.f;
    for (int p = threadIdx.x; p < NQ; p += 1024) {
        float v0 = x[p * 3 + 0], v1 = x[p * 3 + 1], v2 = x[p * 3 + 2];
        s0 += v0; s1 += v1; s2 += v2;
        t0 += v0 * v0; t1 += v1 * v1; t2 += v2 * v2;
    }
#pragma unroll
    for (int o = 16; o; o >>= 1) {
        s0 += __shfl_xor_sync(0xffffffffu, s0, o);
        s1 += __shfl_xor_sync(0xffffffffu, s1, o);
        s2 += __shfl_xor_sync(0xffffffffu, s2, o);
        t0 += __shfl_xor_sync(0xffffffffu, t0, o);
        t1 += __shfl_xor_sync(0xffffffffu, t1, o);
        t2 += __shfl_xor_sync(0xffffffffu, t2, o);
    }
    __shared__ float red[32][6];
    int lane = threadIdx.x & 31, w = threadIdx.x >> 5;
    if (lane == 0) {
        red[w][0] = s0; red[w][1] = s1; red[w][2] = s2;
        red[w][3] = t0; red[w][4] = t1; red[w][5] = t2;
    }
    __syncthreads();
    if (threadIdx.x < 32) {
        float a0 = red[lane][0], a1 = red[lane][1], a2 = red[lane][2];
        float a3 = red[lane][3], a4 = red[lane][4], a5 = red[lane][5];
#pragma unroll
        for (int o = 16; o; o >>= 1) {
            a0 += __shfl_xor_sync(0xffffffffu, a0, o);
            a1 += __shfl_xor_sync(0xffffffffu, a1, o);
            a2 += __shfl_xor_sync(0xffffffffu, a2, o);
            a3 += __shfl_xor_sync(0xffffffffu, a3, o);
            a4 += __shfl_xor_sync(0xffffffffu, a4, o);
            a5 += __shfl_xor_sync(0xffffffffu, a5, o);
        }
        if (lane == 0) {
            const float inv = 1.0f / (float)NQ;
            float m0 = a0 * inv, m1 = a1 * inv, m2 = a2 * inv;
            g_stats[0] = m0; g_stats[1] = m1; g_stats[2] = m2;
            g_stats[4] = rsqrtf(a3 * inv - m0 * m0 + 1e-5f);
            g_stats[5] = rsqrtf(a4 * inv - m1 * m1 + 1e-5f);
            g_stats[6] = rsqrtf(a5 * inv - m2 * m2 + 1e-5f);
        }
    }
}

// ---------------------------------------------------------------------------
// 2) h0 = normalize(x) @ W_in + b_in
// ---------------------------------------------------------------------------
__global__ void input_proj_kernel(const float* __restrict__ x,
                                  const float* __restrict__ W_in,
                                  const float* __restrict__ b_in,
                                  float* __restrict__ h_out,
                                  __half* __restrict__ hf_out) {
    int idx = blockIdx.x * 256 + threadIdx.x;
    int p = idx >> 6, c = idx & 63;
    float acc = b_in[c];
#pragma unroll
    for (int f = 0; f < 3; f++) {
        float xn = (x[p * 3 + f] - g_stats[f]) * g_stats[4 + f];
        acc += xn * W_in[f * 64 + c];
    }
    h_out[idx] = acc;
    hf_out[idx] = __float2half_rn(acc);
}

// ---------------------------------------------------------------------------
// staging
// ---------------------------------------------------------------------------
__device__ __forceinline__ void stage_region(uint32_t sb, const __half* hf,
                                             int pos_rb, int tid) {
    for (int u = tid; u < 1560; u += 256) {
        int r = u >> 3, c4 = u & 7;
        uint32_t dst = sb + (r << 7) + ((c4 ^ (r & 7)) << 4);
        int pos = pos_rb + r;
        int ok = (unsigned)pos < (unsigned)NQ;
        cpa16z(dst, hf + (size_t)(ok ? pos : 0) * 64 + c4 * 8, ok);
    }
}
__device__ __forceinline__ void stage_B(uint32_t dst, const unsigned* w, int tid) {
#pragma unroll
    for (int i = 0; i < 4; i++) {
        int u = tid + (i << 8);             // 0..1023 (16KB)
        cpa16(dst + (u << 4), w + (u << 2));
    }
}

// ---------------------------------------------------------------------------
// 3) Fused attention layer. 8 warps; warp tile = 64 rows x 16 ch (one head):
//    rg = w&1 (rows 64rg..+63), cg = w>>1 (head). Per offset: single A sweep
//    (ldmatrix.x4) feeding K and V mmas, processed in 2 row-halves of 32.
// ---------------------------------------------------------------------------
__global__ __launch_bounds__(256, 2)
void attn_kernel(const float* __restrict__ h_in, const __half* __restrict__ hf,
                 float* __restrict__ h_out, __half* __restrict__ hfo,
                 const unsigned* __restrict__ wq_ph, const float* __restrict__ bq,
                 const unsigned* __restrict__ wkv_ph,
                 const float* __restrict__ bk, const float* __restrict__ bv) {
    extern __shared__ char smem[];
    const uint32_t sb = smem_u32(smem);
    const int tid  = threadIdx.x;
    const int lane = tid & 31;
    const int w    = tid >> 5;
    const int tig  = lane & 3;
    const int l4   = lane >> 2;
    const int rg   = w & 1;
    const int cg   = w >> 1;
    const int lrow = lane & 15;          // ldmatrix row-lane
    const int lhi  = lane >> 4;          // ldmatrix k-half

    const int bx    = blockIdx.x;
    const int tbase = bx << 7;
    const int a0    = (bx & 7) << 2;
    const uint32_t bKoff = (uint32_t)(((cg << 2) << 9)) + (uint32_t)(lane << 4);
    // + (ks<<9) at use site

    // ---- prologue: region(dt=0), Wq -> BB1, B[m=9] -> BB0 ----
    stage_region(sb, hf, tbase - 33, tid);
    for (int u = tid; u < 512; u += 256)
        cpa16(sb + BB1 + (u << 4), wq_ph + (u << 2));
    stage_B(sb + BB0, wkv_ph + 9 * 4096, tid);
    CPA_COMMIT(); CPA_WAIT0();
    __syncthreads();

    // ---- Q projection (region-local base row 33) ----
    unsigned qp[16];
    {
        int rl = 33 + (rg << 6) + lrow;
        uint32_t abase = sb + (rl << 7);
        int xs = rl & 7;
        float qf[32];
#pragma unroll
        for (int e = 0; e < 32; e++) qf[e] = 0.0f;
#pragma unroll
        for (int ks = 0; ks < 4; ks++) {
            unsigned bf[4];
            lds128u(bf, sb + BB1 + bKoff + (ks << 9));
#pragma unroll
            for (int mt = 0; mt < 4; mt++) {
                unsigned a[4];
                ldsm4(a, abase + (mt << 11) + ((unsigned)(((2 * ks + lhi) ^ xs)) << 4));
                mma16(&qf[(mt * 2 + 0) * 4], a, bf[0], bf[1]);
                mma16(&qf[(mt * 2 + 1) * 4], a, bf[2], bf[3]);
            }
        }
#pragma unroll
        for (int mt = 0; mt < 4; mt++)
#pragma unroll
            for (int j = 0; j < 2; j++) {
                float2 b2 = __ldg((const float2*)(bq + 16 * cg + 8 * j) + tig);
#pragma unroll
                for (int rh = 0; rh < 2; rh++)
                    qp[(mt * 2 + j) * 2 + rh] =
                        packh2(qf[(mt * 2 + j) * 4 + rh * 2 + 0] + b2.x,
                               qf[(mt * 2 + j) * 4 + rh * 2 + 1] + b2.y);
            }
    }

    // ---- spatial validity masks for this lane's 8 compute rows ----
    unsigned vm[8];
#pragma unroll
    for (int t = 0; t < 8; t++) {
        int lr = (rg << 6) + l4 + ((t >> 1) << 4) + ((t & 1) << 3);
        int ga = a0 + (lr >> 5), gb = lr & 31;
        bool aM = (ga > 0), aP = (ga < 31), bM = (gb > 0), bP = (gb < 31);
        unsigned v = 0;
#pragma unroll
        for (int m = 0; m < MOFF; m++) {
            int r9 = m % 9;
            int di = r9 / 3 - 1, dj = r9 % 3 - 1;
            bool ok = (di < 0 ? aM : (di > 0 ? aP : true)) &&
                      (dj < 0 ? bM : (dj > 0 ? bP : true));
            v |= ((unsigned)ok) << m;
        }
        vm[t] = v;
    }

    float acc[32], den[8];
#pragma unroll
    for (int e = 0; e < 32; e++) acc[e] = 0.0f;
#pragma unroll
    for (int t = 0; t < 8; t++) den[t] = 0.0f;

    // ---- 27-offset mainloop (dt-grouped: 9..17, 0..8, 18..26) ----
#pragma unroll 1
    for (int i = 0; i < MOFF; i++) {
        int m = i + (i < 9 ? 9 : (i < 18 ? -9 : 0));
        CPA_WAIT0();
        __syncthreads();
        if (i < 26) {
            int mn = i + 1;
            mn += (mn < 9 ? 9 : (mn < 18 ? -9 : 0));
            stage_B(sb + ((i & 1) ? BB0 : BB1), wkv_ph + mn * 4096, tid);
            CPA_COMMIT();
        }
        const uint32_t bB = sb + ((i & 1) ? BB1 : BB0);
        int r9 = m % 9;
        int di = r9 / 3 - 1, dj = r9 % 3 - 1;

        int rl = 33 + di * 32 + dj + (rg << 6) + lrow;
        uint32_t abase = sb + (rl << 7);
        int xs = rl & 7;

        // two row-halves of 32 rows each; fused K+V on one A sweep
#pragma unroll
        for (int hf2 = 0; hf2 < 2; hf2++) {
            float dK[16], dV[16];
#pragma unroll
            for (int e = 0; e < 16; e++) { dK[e] = 0.0f; dV[e] = 0.0f; }
#pragma unroll
            for (int ks = 0; ks < 4; ks++) {
                unsigned bkf[4], bvf[4];
                lds128u(bkf, bB + bKoff + (ks << 9));
                lds128u(bvf, bB + 8192u + bKoff + (ks << 9));
#pragma unroll
                for (int mtl = 0; mtl < 2; mtl++) {
                    int mt = hf2 * 2 + mtl;
                    unsigned a[4];
                    ldsm4(a, abase + (mt << 11) +
                              ((unsigned)(((2 * ks + lhi) ^ xs)) << 4));
                    mma16(&dK[mtl * 8 + 0], a, bkf[0], bkf[1]);
                    mma16(&dK[mtl * 8 + 4], a, bkf[2], bkf[3]);
                    mma16(&dV[mtl * 8 + 0], a, bvf[0], bvf[1]);
                    mma16(&dV[mtl * 8 + 4], a, bvf[2], bvf[3]);
                }
            }
            // scores for the 4 (mtl, rh) rows of this half
            float sp[4];
#pragma unroll
            for (int t = 0; t < 4; t++) sp[t] = 0.0f;
#pragma unroll
            for (int mtl = 0; mtl < 2; mtl++)
#pragma unroll
                for (int j = 0; j < 2; j++) {
                    int mt = hf2 * 2 + mtl;
                    float2 bk2 = __ldg((const float2*)(bk + m * 64 + 16 * cg + 8 * j) + tig);
#pragma unroll
                    for (int rh = 0; rh < 2; rh++) {
                        float2 qv = unpackh2(qp[(mt * 2 + j) * 2 + rh]);
                        float k0 = dK[mtl * 8 + j * 4 + rh * 2 + 0] + bk2.x;
                        float k1 = dK[mtl * 8 + j * 4 + rh * 2 + 1] + bk2.y;
                        sp[mtl * 2 + rh] += k0 * qv.x + k1 * qv.y;
                    }
                }
            float p[4];
#pragma unroll
            for (int t = 0; t < 4; t++) {
                float s = sp[t];
                s += __shfl_xor_sync(0xffffffffu, s, 1);
                s += __shfl_xor_sync(0xffffffffu, s, 2);
                int gt = hf2 * 4 + ((t >> 1) << 1) + (t & 1);   // (hf2*2+mtl)*2+rh
                bool ok = (vm[gt] >> m) & 1u;
                float pv = __expf(ok ? s : -1e30f);
                p[t] = pv;
                den[gt] += pv;
            }
            // apply
#pragma unroll
            for (int mtl = 0; mtl < 2; mtl++)
#pragma unroll
                for (int j = 0; j < 2; j++) {
                    int mt = hf2 * 2 + mtl;
                    float2 bv2 = __ldg((const float2*)(bv + m * 64 + 16 * cg + 8 * j) + tig);
#pragma unroll
                    for (int rh = 0; rh < 2; rh++) {
                        float pw = p[mtl * 2 + rh];
                        acc[(mt * 2 + j) * 4 + rh * 2 + 0] +=
                            pw * (dV[mtl * 8 + j * 4 + rh * 2 + 0] + bv2.x);
                        acc[(mt * 2 + j) * 4 + rh * 2 + 1] +=
                            pw * (dV[mtl * 8 + j * 4 + rh * 2 + 1] + bv2.y);
                    }
                }
        }

        if (i == 8 || i == 17) {
            __syncthreads();
            int dt = (i == 8) ? -1 : 1;
            stage_region(sb, hf, tbase + dt * 1024 - 33, tid);
            CPA_COMMIT();
        }
    }

    // ---- epilogue: per-row normalize + residual + store ----
#pragma unroll
    for (int mt = 0; mt < 4; mt++)
#pragma unroll
        for (int rh = 0; rh < 2; rh++) {
            int pos = tbase + (rg << 6) + l4 + (mt << 4) + (rh << 3);
            float iv = 1.0f / den[mt * 2 + rh];
            const float* rp = h_in + ((size_t)pos << 6);
            float* op = h_out + ((size_t)pos << 6);
#pragma unroll
            for (int j = 0; j < 2; j++) {
                int c = 16 * cg + 8 * j + 2 * tig;
                float2 r = *(const float2*)(rp + c);
                float ox = acc[(mt * 2 + j) * 4 + rh * 2 + 0] * iv + r.x;
                float oy = acc[(mt * 2 + j) * 4 + rh * 2 + 1] * iv + r.y;
                float2 o; o.x = ox; o.y = oy;
                *(float2*)(op + c) = o;
                if (hfo) {
                    __half2 h2 = __floats2half2_rn(ox, oy);
                    *(unsigned*)(&hfo[(size_t)pos * 64 + c]) = *(unsigned*)&h2;
                }
            }
        }
}

// ---------------------------------------------------------------------------
// 4) out = h @ W_out + b_out
// ---------------------------------------------------------------------------
__global__ void out_proj_kernel(const float* __restrict__ h,
                                const float* __restrict__ W_out,
                                const float* __restrict__ b_out,
                                float* __restrict__ out) {
    __shared__ float hs[32 * 64];
    int tid = threadIdx.x;
    int base = blockIdx.x * 32;
    for (int j = tid; j < 2048; j += 128) hs[j] = h[base * 64 + j];
    __syncthreads();
    if (tid < 96) {
        int rr = tid / 3, f = tid - 3 * (tid / 3);
        float acc = b_out[f];
#pragma unroll 8
        for (int cp = 0; cp < 64; cp++)
            acc += hs[rr * 64 + cp] * W_out[cp * 3 + f];
        out[(base + rr) * 3 + f] = acc;
    }
}

// ---------------------------------------------------------------------------
extern "C" void kernel_launch(void* const* d_in, const int* in_sizes, int n_in,
                              void* d_out, int out_size) {
    const float* x     = (const float*)d_in[0];
    const float* W_in  = (const float*)d_in[1];
    const float* b_in  = (const float*)d_in[2];
    const float* W_out = (const float*)d_in[3];
    const float* b_out = (const float*)d_in[4];
    const float* Wq    = (const float*)d_in[5];
    const float* bq    = (const float*)d_in[6];
    const float* Wk    = (const float*)d_in[7];
    const float* bk    = (const float*)d_in[8];
    const float* Wv    = (const float*)d_in[9];
    const float* bv    = (const float*)d_in[10];
    float* out = (float*)d_out;

    float *h0, *h1;
    __half *hf0, *hf1;
    unsigned *wq_ph, *wkv_ph;
    cudaGetSymbolAddress((void**)&h0, g_h0);
    cudaGetSymbolAddress((void**)&h1, g_h1);
    cudaGetSymbolAddress((void**)&hf0, g_hf0);
    cudaGetSymbolAddress((void**)&hf1, g_hf1);
    cudaGetSymbolAddress((void**)&wq_ph, g_wq_ph);
    cudaGetSymbolAddress((void**)&wkv_ph, g_wkv_ph);
    cudaFuncSetAttribute(attn_kernel, cudaFuncAttributeMaxDynamicSharedMemorySize, SMEMB);

    repack_w_kernel<<<(54 * 2048 + 255) / 256, 256>>>(Wq, Wk, Wv);
    bn_stats_kernel<<<1, 1024>>>(x);
    input_proj_kernel<<<(NQ * 64) / 256, 256>>>(x, W_in, b_in, h0, hf0);

    attn_kernel<<<256, 256, SMEMB>>>(h0, hf0, h1, hf1,
        wq_ph, bq, wkv_ph, bk, bv);
    attn_kernel<<<256, 256, SMEMB>>>(h1, hf1, h0, (__half*)nullptr,
        wq_ph + 2048, bq + 64, wkv_ph + 27 * 4096, bk + 27 * 64, bv + 27 * 64);

    out_proj_kernel<<<NQ / 32, 128>>>(h0, W_out, b_out, out);
}

// round 11
// speedup vs baseline: 8.4121x; 1.0018x over previous
#include <cuda_runtime.h>
#include <cuda_fp16.h>
#include <math.h>
#include <stdint.h>

#define NQ   32768
#define MOFF 27

// smem: A region (195 rows x 128B fp16) + 2 B buffers (16KB) + biases
#define ARH    0
#define BB0    24960
#define BB1    41344
#define BIASK  57728     // 27*64 fp32 = 6912B
#define BIASV  64640     // 6912B
#define BIASQ  71552     // 256B
#define SMEMB  71808

// Scratch (static device globals: allocation-free per harness rules)
__device__ float g_h0[NQ * 64];
__device__ float g_h1[NQ * 64];
__device__ __half g_hf0[NQ * 64];
__device__ __half g_hf1[NQ * 64];
__device__ float g_stats[8];
__device__ unsigned g_wq_ph[2 * 2048];     // per layer: lds128-frag-packed fp16 Wq^T
__device__ unsigned g_wkv_ph[54 * 4096];   // per (layer,m): [K 2048 | V 2048] u32

// ---------------------------------------------------------------------------
__device__ __forceinline__ uint32_t smem_u32(const void* p) {
    uint32_t a;
    asm("{ .reg .u64 t; cvta.to.shared.u64 t, %1; cvt.u32.u64 %0, t; }" : "=r"(a) : "l"(p));
    return a;
}
__device__ __forceinline__ void cpa16z(uint32_t dst, const void* src, int ok) {
    asm volatile("cp.async.cg.shared.global [%0], [%1], 16, %2;"
                 :: "r"(dst), "l"(src), "r"(ok ? 16 : 0));
}
__device__ __forceinline__ void cpa16(uint32_t dst, const void* src) {
    asm volatile("cp.async.cg.shared.global [%0], [%1], 16;" :: "r"(dst), "l"(src));
}
#define CPA_COMMIT() asm volatile("cp.async.commit_group;" ::: "memory")
#define CPA_WAIT0()  asm volatile("cp.async.wait_group 0;"  ::: "memory")

__device__ __forceinline__ void lds128u(unsigned* v, uint32_t a) {
    asm volatile("ld.shared.v4.b32 {%0, %1, %2, %3}, [%4];"
                 : "=r"(v[0]), "=r"(v[1]), "=r"(v[2]), "=r"(v[3]) : "r"(a));
}
__device__ __forceinline__ float2 lds64f(uint32_t a) {
    float2 v;
    asm volatile("ld.shared.v2.f32 {%0, %1}, [%2];" : "=f"(v.x), "=f"(v.y) : "r"(a));
    return v;
}
// ldmatrix x4 (sm_75+ baseline): 4 8x8 b16 matrices, per-lane row pointers
__device__ __forceinline__ void ldsm4(unsigned* r, uint32_t a) {
    asm volatile("ldmatrix.sync.aligned.m8n8.x4.shared.b16 {%0, %1, %2, %3}, [%4];"
                 : "=r"(r[0]), "=r"(r[1]), "=r"(r[2]), "=r"(r[3]) : "r"(a));
}
// fp16 tensor-core mma (sm_80+ baseline): D(16x8,f32) += A(16x16) * B(16x8)
__device__ __forceinline__ void mma16(float* d, const unsigned* a, unsigned b0, unsigned b1) {
    asm volatile(
        "mma.sync.aligned.m16n8k16.row.col.f32.f16.f16.f32 "
        "{%0,%1,%2,%3}, {%4,%5,%6,%7}, {%8,%9}, {%0,%1,%2,%3};"
        : "+f"(d[0]), "+f"(d[1]), "+f"(d[2]), "+f"(d[3])
        : "r"(a[0]), "r"(a[1]), "r"(a[2]), "r"(a[3]), "r"(b0), "r"(b1));
}
__device__ __forceinline__ unsigned packh2(float x, float y) {
    __half2 t = __floats2half2_rn(x, y);
    return *reinterpret_cast<unsigned*>(&t);
}
__device__ __forceinline__ float2 unpackh2(unsigned u) {
    __half2 t = *reinterpret_cast<__half2*>(&u);
    return __half22float2(t);
}

// ---------------------------------------------------------------------------
// 0) Weight repack to lds128 fragment layout (same as R10).
// ---------------------------------------------------------------------------
__global__ void repack_w_kernel(const float* __restrict__ Wq,
                                const float* __restrict__ Wk,
                                const float* __restrict__ Wv) {
    int idx = blockIdx.x * 256 + threadIdx.x;
    if (idx >= 54 * 2048) return;
    int mi = idx >> 11, e = idx & 2047;
    int cg = e >> 9, ks = (e >> 7) & 3, lane = (e >> 2) & 31, u = e & 3;
    int cin  = 16 * ks + 2 * (lane & 3) + 8 * (u & 1);
    int cout = 16 * cg + 8 * (u >> 1) + (lane >> 2);
    int s0 = mi * 4096 + cin * 64 + cout;
    g_wkv_ph[mi * 4096 + e]        = packh2(Wk[s0], Wk[s0 + 64]);
    g_wkv_ph[mi * 4096 + 2048 + e] = packh2(Wv[s0], Wv[s0 + 64]);
    if (mi < 2)
        g_wq_ph[mi * 2048 + e] = packh2(Wq[s0], Wq[s0 + 64]);
}

// ---------------------------------------------------------------------------
// 1) BatchNorm batch statistics
// ---------------------------------------------------------------------------
__global__ void bn_stats_kernel(const float* __restrict__ x) {
    float s0 = 0.f, s1 = 0.f, s2 = 0.f, t0 = 0.f, t1 = 0.f, t2 = 0.f;
    for (int p = threadIdx.x; p < NQ; p += 1024) {
        float v0 = x[p * 3 + 0], v1 = x[p * 3 + 1], v2 = x[p * 3 + 2];
        s0 += v0; s1 += v1; s2 += v2;
        t0 += v0 * v0; t1 += v1 * v1; t2 += v2 * v2;
    }
#pragma unroll
    for (int o = 16; o; o >>= 1) {
        s0 += __shfl_xor_sync(0xffffffffu, s0, o);
        s1 += __shfl_xor_sync(0xffffffffu, s1, o);
        s2 += __shfl_xor_sync(0xffffffffu, s2, o);
        t0 += __shfl_xor_sync(0xffffffffu, t0, o);
        t1 += __shfl_xor_sync(0xffffffffu, t1, o);
        t2 += __shfl_xor_sync(0xffffffffu, t2, o);
    }
    __shared__ float red[32][6];
    int lane = threadIdx.x & 31, w = threadIdx.x >> 5;
    if (lane == 0) {
        red[w][0] = s0; red[w][1] = s1; red[w][2] = s2;
        red[w][3] = t0; red[w][4] = t1; red[w][5] = t2;
    }
    __syncthreads();
    if (threadIdx.x < 32) {
        float a0 = red[lane][0], a1 = red[lane][1], a2 = red[lane][2];
        float a3 = red[lane][3], a4 = red[lane][4], a5 = red[lane][5];
#pragma unroll
        for (int o = 16; o; o >>= 1) {
            a0 += __shfl_xor_sync(0xffffffffu, a0, o);
            a1 += __shfl_xor_sync(0xffffffffu, a1, o);
            a2 += __shfl_xor_sync(0xffffffffu, a2, o);
            a3 += __shfl_xor_sync(0xffffffffu, a3, o);
            a4 += __shfl_xor_sync(0xffffffffu, a4, o);
            a5 += __shfl_xor_sync(0xffffffffu, a5, o);
        }
        if (lane == 0) {
            const float inv = 1.0f / (float)NQ;
            float m0 = a0 * inv, m1 = a1 * inv, m2 = a2 * inv;
            g_stats[0] = m0; g_stats[1] = m1; g_stats[2] = m2;
            g_stats[4] = rsqrtf(a3 * inv - m0 * m0 + 1e-5f);
            g_stats[5] = rsqrtf(a4 * inv - m1 * m1 + 1e-5f);
            g_stats[6] = rsqrtf(a5 * inv - m2 * m2 + 1e-5f);
        }
    }
}

// ---------------------------------------------------------------------------
// 2) h0 = normalize(x) @ W_in + b_in
// ---------------------------------------------------------------------------
__global__ void input_proj_kernel(const float* __restrict__ x,
                                  const float* __restrict__ W_in,
                                  const float* __restrict__ b_in,
                                  float* __restrict__ h_out,
                                  __half* __restrict__ hf_out) {
    int idx = blockIdx.x * 256 + threadIdx.x;
    int p = idx >> 6, c = idx & 63;
    float acc = b_in[c];
#pragma unroll
    for (int f = 0; f < 3; f++) {
        float xn = (x[p * 3 + f] - g_stats[f]) * g_stats[4 + f];
        acc += xn * W_in[f * 64 + c];
    }
    h_out[idx] = acc;
    hf_out[idx] = __float2half_rn(acc);
}

// ---------------------------------------------------------------------------
// staging
// ---------------------------------------------------------------------------
__device__ __forceinline__ void stage_region(uint32_t sb, const __half* hf,
                                             int pos_rb, int tid) {
    for (int u = tid; u < 1560; u += 256) {
        int r = u >> 3, c4 = u & 7;
        uint32_t dst = sb + (r << 7) + ((c4 ^ (r & 7)) << 4);
        int pos = pos_rb + r;
        int ok = (unsigned)pos < (unsigned)NQ;
        cpa16z(dst, hf + (size_t)(ok ? pos : 0) * 64 + c4 * 8, ok);
    }
}
__device__ __forceinline__ void stage_B(uint32_t dst, const unsigned* w, int tid) {
#pragma unroll
    for (int i = 0; i < 4; i++) {
        int u = tid + (i << 8);             // 0..1023 (16KB)
        cpa16(dst + (u << 4), w + (u << 2));
    }
}

// ---------------------------------------------------------------------------
// 3) Fused attention layer (R10 structure + smem-staged biases).
// ---------------------------------------------------------------------------
__global__ __launch_bounds__(256, 2)
void attn_kernel(const float* __restrict__ h_in, const __half* __restrict__ hf,
                 float* __restrict__ h_out, __half* __restrict__ hfo,
                 const unsigned* __restrict__ wq_ph, const float* __restrict__ bq,
                 const unsigned* __restrict__ wkv_ph,
                 const float* __restrict__ bk, const float* __restrict__ bv) {
    extern __shared__ char smem[];
    const uint32_t sb = smem_u32(smem);
    const int tid  = threadIdx.x;
    const int lane = tid & 31;
    const int w    = tid >> 5;
    const int tig  = lane & 3;
    const int l4   = lane >> 2;
    const int rg   = w & 1;
    const int cg   = w >> 1;
    const int lrow = lane & 15;
    const int lhi  = lane >> 4;

    const int bx    = blockIdx.x;
    const int tbase = bx << 7;
    const int a0    = (bx & 7) << 2;
    const uint32_t bKoff = (uint32_t)(((cg << 2) << 9)) + (uint32_t)(lane << 4);
    const uint32_t biasOff = (uint32_t)((cg << 6) + (tig << 3));  // ch byte offset

    // ---- prologue: region(dt=0), Wq -> BB1, B[m=9] -> BB0, biases ----
    stage_region(sb, hf, tbase - 33, tid);
    for (int u = tid; u < 512; u += 256)
        cpa16(sb + BB1 + (u << 4), wq_ph + (u << 2));
    stage_B(sb + BB0, wkv_ph + 9 * 4096, tid);
    for (int u = tid; u < 880; u += 256) {
        if (u < 432)      cpa16(sb + BIASK + (u << 4), bk + (u << 2));
        else if (u < 864) cpa16(sb + BIASV + ((u - 432) << 4), bv + ((u - 432) << 2));
        else              cpa16(sb + BIASQ + ((u - 864) << 4), bq + ((u - 864) << 2));
    }
    CPA_COMMIT(); CPA_WAIT0();
    __syncthreads();

    // ---- Q projection (region-local base row 33) ----
    unsigned qp[16];
    {
        int rl = 33 + (rg << 6) + lrow;
        uint32_t abase = sb + (rl << 7);
        int xs = rl & 7;
        float qf[32];
#pragma unroll
        for (int e = 0; e < 32; e++) qf[e] = 0.0f;
#pragma unroll
        for (int ks = 0; ks < 4; ks++) {
            unsigned bf[4];
            lds128u(bf, sb + BB1 + bKoff + (ks << 9));
#pragma unroll
            for (int mt = 0; mt < 4; mt++) {
                unsigned a[4];
                ldsm4(a, abase + (mt << 11) + ((unsigned)(((2 * ks + lhi) ^ xs)) << 4));
                mma16(&qf[(mt * 2 + 0) * 4], a, bf[0], bf[1]);
                mma16(&qf[(mt * 2 + 1) * 4], a, bf[2], bf[3]);
            }
        }
        float2 bq0 = lds64f(sb + BIASQ + biasOff);
        float2 bq1 = lds64f(sb + BIASQ + biasOff + 32);
#pragma unroll
        for (int mt = 0; mt < 4; mt++)
#pragma unroll
            for (int j = 0; j < 2; j++) {
                float2 b2 = j ? bq1 : bq0;
#pragma unroll
                for (int rh = 0; rh < 2; rh++)
                    qp[(mt * 2 + j) * 2 + rh] =
                        packh2(qf[(mt * 2 + j) * 4 + rh * 2 + 0] + b2.x,
                               qf[(mt * 2 + j) * 4 + rh * 2 + 1] + b2.y);
            }
    }

    // ---- spatial validity masks ----
    unsigned vm[8];
#pragma unroll
    for (int t = 0; t < 8; t++) {
        int lr = (rg << 6) + l4 + ((t >> 1) << 4) + ((t & 1) << 3);
        int ga = a0 + (lr >> 5), gb = lr & 31;
        bool aM = (ga > 0), aP = (ga < 31), bM = (gb > 0), bP = (gb < 31);
        unsigned v = 0;
#pragma unroll
        for (int m = 0; m < MOFF; m++) {
            int r9 = m % 9;
            int di = r9 / 3 - 1, dj = r9 % 3 - 1;
            bool ok = (di < 0 ? aM : (di > 0 ? aP : true)) &&
                      (dj < 0 ? bM : (dj > 0 ? bP : true));
            v |= ((unsigned)ok) << m;
        }
        vm[t] = v;
    }

    float acc[32], den[8];
#pragma unroll
    for (int e = 0; e < 32; e++) acc[e] = 0.0f;
#pragma unroll
    for (int t = 0; t < 8; t++) den[t] = 0.0f;

    // ---- 27-offset mainloop (dt-grouped: 9..17, 0..8, 18..26) ----
#pragma unroll 1
    for (int i = 0; i < MOFF; i++) {
        int m = i + (i < 9 ? 9 : (i < 18 ? -9 : 0));
        CPA_WAIT0();
        __syncthreads();
        if (i < 26) {
            int mn = i + 1;
            mn += (mn < 9 ? 9 : (mn < 18 ? -9 : 0));
            stage_B(sb + ((i & 1) ? BB0 : BB1), wkv_ph + mn * 4096, tid);
            CPA_COMMIT();
        }
        const uint32_t bB = sb + ((i & 1) ? BB1 : BB0);
        int r9 = m % 9;
        int di = r9 / 3 - 1, dj = r9 % 3 - 1;

        // biases for this offset (smem, issued early — latency hidden by mmas)
        float2 bk2[2], bv2[2];
        bk2[0] = lds64f(sb + BIASK + (m << 8) + biasOff);
        bk2[1] = lds64f(sb + BIASK + (m << 8) + biasOff + 32);
        bv2[0] = lds64f(sb + BIASV + (m << 8) + biasOff);
        bv2[1] = lds64f(sb + BIASV + (m << 8) + biasOff + 32);

        int rl = 33 + di * 32 + dj + (rg << 6) + lrow;
        uint32_t abase = sb + (rl << 7);
        int xs = rl & 7;

#pragma unroll
        for (int hf2 = 0; hf2 < 2; hf2++) {
            float dK[16], dV[16];
#pragma unroll
            for (int e = 0; e < 16; e++) { dK[e] = 0.0f; dV[e] = 0.0f; }
#pragma unroll
            for (int ks = 0; ks < 4; ks++) {
                unsigned bkf[4], bvf[4];
                lds128u(bkf, bB + bKoff + (ks << 9));
                lds128u(bvf, bB + 8192u + bKoff + (ks << 9));
#pragma unroll
                for (int mtl = 0; mtl < 2; mtl++) {
                    int mt = hf2 * 2 + mtl;
                    unsigned a[4];
                    ldsm4(a, abase + (mt << 11) +
                              ((unsigned)(((2 * ks + lhi) ^ xs)) << 4));
                    mma16(&dK[mtl * 8 + 0], a, bkf[0], bkf[1]);
                    mma16(&dK[mtl * 8 + 4], a, bkf[2], bkf[3]);
                    mma16(&dV[mtl * 8 + 0], a, bvf[0], bvf[1]);
                    mma16(&dV[mtl * 8 + 4], a, bvf[2], bvf[3]);
                }
            }
            float sp[4];
#pragma unroll
            for (int t = 0; t < 4; t++) sp[t] = 0.0f;
#pragma unroll
            for (int mtl = 0; mtl < 2; mtl++)
#pragma unroll
                for (int j = 0; j < 2; j++) {
                    int mt = hf2 * 2 + mtl;
#pragma unroll
                    for (int rh = 0; rh < 2; rh++) {
                        float2 qv = unpackh2(qp[(mt * 2 + j) * 2 + rh]);
                        float k0 = dK[mtl * 8 + j * 4 + rh * 2 + 0] + bk2[j].x;
                        float k1 = dK[mtl * 8 + j * 4 + rh * 2 + 1] + bk2[j].y;
                        sp[mtl * 2 + rh] += k0 * qv.x + k1 * qv.y;
                    }
                }
            float p[4];
#pragma unroll
            for (int t = 0; t < 4; t++) {
                float s = sp[t];
                s += __shfl_xor_sync(0xffffffffu, s, 1);
                s += __shfl_xor_sync(0xffffffffu, s, 2);
                int gt = hf2 * 4 + ((t >> 1) << 1) + (t & 1);
                bool ok = (vm[gt] >> m) & 1u;
                float pv = __expf(ok ? s : -1e30f);
                p[t] = pv;
                den[gt] += pv;
            }
#pragma unroll
            for (int mtl = 0; mtl < 2; mtl++)
#pragma unroll
                for (int j = 0; j < 2; j++) {
                    int mt = hf2 * 2 + mtl;
#pragma unroll
                    for (int rh = 0; rh < 2; rh++) {
                        float pw = p[mtl * 2 + rh];
                        acc[(mt * 2 + j) * 4 + rh * 2 + 0] +=
                            pw * (dV[mtl * 8 + j * 4 + rh * 2 + 0] + bv2[j].x);
                        acc[(mt * 2 + j) * 4 + rh * 2 + 1] +=
                            pw * (dV[mtl * 8 + j * 4 + rh * 2 + 1] + bv2[j].y);
                    }
                }
        }

        if (i == 8 || i == 17) {
            __syncthreads();
            int dt = (i == 8) ? -1 : 1;
            stage_region(sb, hf, tbase + dt * 1024 - 33, tid);
            CPA_COMMIT();
        }
    }

    // ---- epilogue ----
#pragma unroll
    for (int mt = 0; mt < 4; mt++)
#pragma unroll
        for (int rh = 0; rh < 2; rh++) {
            int pos = tbase + (rg << 6) + l4 + (mt << 4) + (rh << 3);
            float iv = 1.0f / den[mt * 2 + rh];
            const float* rp = h_in + ((size_t)pos << 6);
            float* op = h_out + ((size_t)pos << 6);
#pragma unroll
            for (int j = 0; j < 2; j++) {
                int c = 16 * cg + 8 * j + 2 * tig;
                float2 r = *(const float2*)(rp + c);
                float ox = acc[(mt * 2 + j) * 4 + rh * 2 + 0] * iv + r.x;
                float oy = acc[(mt * 2 + j) * 4 + rh * 2 + 1] * iv + r.y;
                float2 o; o.x = ox; o.y = oy;
                *(float2*)(op + c) = o;
                if (hfo) {
                    __half2 h2 = __floats2half2_rn(ox, oy);
                    *(unsigned*)(&hfo[(size_t)pos * 64 + c]) = *(unsigned*)&h2;
                }
            }
        }
}

// ---------------------------------------------------------------------------
// 4) out = h @ W_out + b_out
// ---------------------------------------------------------------------------
__global__ void out_proj_kernel(const float* __restrict__ h,
                                const float* __restrict__ W_out,
                                const float* __restrict__ b_out,
                                float* __restrict__ out) {
    __shared__ float hs[32 * 64];
    int tid = threadIdx.x;
    int base = blockIdx.x * 32;
    for (int j = tid; j < 2048; j += 128) hs[j] = h[base * 64 + j];
    __syncthreads();
    if (tid < 96) {
        int rr = tid / 3, f = tid - 3 * (tid / 3);
        float acc = b_out[f];
#pragma unroll 8
        for (int cp = 0; cp < 64; cp++)
            acc += hs[rr * 64 + cp] * W_out[cp * 3 + f];
        out[(base + rr) * 3 + f] = acc;
    }
}

// ---------------------------------------------------------------------------
extern "C" void kernel_launch(void* const* d_in, const int* in_sizes, int n_in,
                              void* d_out, int out_size) {
    const float* x     = (const float*)d_in[0];
    const float* W_in  = (const float*)d_in[1];
    const float* b_in  = (const float*)d_in[2];
    const float* W_out = (const float*)d_in[3];
    const float* b_out = (const float*)d_in[4];
    const float* Wq    = (const float*)d_in[5];
    const float* bq    = (const float*)d_in[6];
    const float* Wk    = (const float*)d_in[7];
    const float* bk    = (const float*)d_in[8];
    const float* Wv    = (const float*)d_in[9];
    const float* bv    = (const float*)d_in[10];
    float* out = (float*)d_out;

    float *h0, *h1;
    __half *hf0, *hf1;
    unsigned *wq_ph, *wkv_ph;
    cudaGetSymbolAddress((void**)&h0, g_h0);
    cudaGetSymbolAddress((void**)&h1, g_h1);
    cudaGetSymbolAddress((void**)&hf0, g_hf0);
    cudaGetSymbolAddress((void**)&hf1, g_hf1);
    cudaGetSymbolAddress((void**)&wq_ph, g_wq_ph);
    cudaGetSymbolAddress((void**)&wkv_ph, g_wkv_ph);
    cudaFuncSetAttribute(attn_kernel, cudaFuncAttributeMaxDynamicSharedMemorySize, SMEMB);

    repack_w_kernel<<<(54 * 2048 + 255) / 256, 256>>>(Wq, Wk, Wv);
    bn_stats_kernel<<<1, 1024>>>(x);
    input_proj_kernel<<<(NQ * 64) / 256, 256>>>(x, W_in, b_in, h0, hf0);

    attn_kernel<<<256, 256, SMEMB>>>(h0, hf0, h1, hf1,
        wq_ph, bq, wkv_ph, bk, bv);
    attn_kernel<<<256, 256, SMEMB>>>(h1, hf1, h0, (__half*)nullptr,
        wq_ph + 2048, bq + 64, wkv_ph + 27 * 4096, bk + 27 * 64, bv + 27 * 64);

    out_proj_kernel<<<NQ / 32, 128>>>(h0, W_out, b_out, out);
}